// round 9
// baseline (speedup 1.0000x reference)
#include <cuda_runtime.h>
#include <cuda_fp16.h>
#include <math.h>
#include <stdint.h>

#define B_ 16
#define S_ 2048
#define D_ 256
#define NT 128
#define LOG2E 1.4426950408889634f

// ================= fp16 hi/lo split scratch (K, V only) =================
__device__ __half g_Kthi[(size_t)B_*S_*D_];  // [b][j][d]
__device__ __half g_Ktlo[(size_t)B_*S_*D_];
__device__ __half g_Vthi[(size_t)B_*S_*D_];  // [b][dv][j]

__device__ __forceinline__ uint32_t smem_u32(const void* p) {
    uint32_t a;
    asm("{ .reg .u64 t; cvta.to.shared.u64 t, %1; cvt.u32.u64 %0, t; }" : "=r"(a) : "l"(p));
    return a;
}

// fast exp2 on fma/alu pipes (no MUFU)
__device__ __forceinline__ float exp2p(float y) {
    y = fmaxf(y, -125.f);
    float z = __fadd_rn(y, 12582912.f);
    int   n = __float_as_int(z) - 0x4B400000;
    float f = __fsub_rn(y, __fadd_rn(z, -12582912.f));
    float p = 1.33335581e-3f;
    p = fmaf(p, f, 9.61812910e-3f);
    p = fmaf(p, f, 5.55041087e-2f);
    p = fmaf(p, f, 2.40226512e-1f);
    p = fmaf(p, f, 6.93147182e-1f);
    p = fmaf(p, f, 1.0f);
    return __int_as_float(__float_as_int(p) + (n << 23));
}

#define LDSM4(r, a) \
    asm volatile("ldmatrix.sync.aligned.m8n8.x4.shared.b16 {%0,%1,%2,%3}, [%4];" \
        : "=r"((r)[0]), "=r"((r)[1]), "=r"((r)[2]), "=r"((r)[3]) : "r"(a))

#define MMA(d, a, b0, b1) \
    asm volatile("mma.sync.aligned.m16n8k16.row.col.f32.f16.f16.f32 " \
        "{%0,%1,%2,%3},{%4,%5,%6,%7},{%8,%9},{%0,%1,%2,%3};" \
        : "+f"((d)[0]), "+f"((d)[1]), "+f"((d)[2]), "+f"((d)[3]) \
        : "r"((a)[0]), "r"((a)[1]), "r"((a)[2]), "r"((a)[3]), "r"(b0), "r"(b1))

#define PACKH2(d, lo, hi) \
    asm("cvt.rn.f16x2.f32 %0, %1, %2;" : "=r"(d) : "f"(hi), "f"(lo))

#define CPASYNC16(dst, src) \
    asm volatile("cp.async.cg.shared.global [%0], [%1], 16;" :: "r"(dst), "l"(src))
#define CPCOMMIT() asm volatile("cp.async.commit_group;" ::: "memory")
#define CPWAIT0()  asm volatile("cp.async.wait_group 0;" ::: "memory")

// ================= prep kernel =================
// in [b][R][C] fp32 -> transposed fp16. which=0: K (hi+lo), which=1: V (hi only)
__global__ void transpose_split_kernel(const float* __restrict__ in, int R, int C, int which) {
    __shared__ float t[32][33];
    int b = blockIdx.z;
    int r0 = blockIdx.y * 32, c0 = blockIdx.x * 32;
    const float* ib = in + (size_t)b * R * C;
    for (int rr = threadIdx.y; rr < 32; rr += 8)
        t[rr][threadIdx.x] = ib[(size_t)(r0 + rr) * C + c0 + threadIdx.x];
    __syncthreads();
    __half* oh = (which ? g_Vthi : g_Kthi) + (size_t)b * R * C;
    for (int cc = threadIdx.y; cc < 32; cc += 8) {
        float x = t[threadIdx.x][cc];
        __half h = __float2half_rn(x);
        size_t o = (size_t)(c0 + cc) * R + r0 + threadIdx.x;
        oh[o] = h;
        if (which == 0)
            g_Ktlo[(size_t)b * R * C + o] = __float2half_rn(x - __half2float(h));
    }
}

// ================= main kernel =================
// Q/K rows are 512 B; swizzle (r,u): off = r*512 + ((u^(r&7))<<4)
// V rows are 64 B;  swizzle (r,u): off = r*64  + ((u^((r>>1)&3))<<4)
#define ROWQ   512
#define QSP    32768
#define OFF_K  65536
#define KSP    16384
#define OFF_V  98304
#define ROWV   64
#define SMEM_SZ 114688

__global__ void __launch_bounds__(NT, 2)
attn_hmma(const float* __restrict__ qf,
          const int* __restrict__ mask, float* __restrict__ out)
{
    extern __shared__ char smem[];
    const uint32_t sb = smem_u32(smem);
    const int tid  = threadIdx.x;
    const int lane = tid & 31;
    const int warp = tid >> 5;
    const int b    = blockIdx.y;
    const int q0   = blockIdx.x * 64;

    const __half* kh_b = g_Kthi + (size_t)b * S_ * D_;
    const __half* kl_b = g_Ktlo + (size_t)b * S_ * D_;
    const __half* vh_b = g_Vthi + (size_t)b * D_ * S_;
    const float*  qsrc = qf + ((size_t)b * S_ + q0) * D_;

    // ---- prologue: load Q fp32 through K buffer (2 passes), split to hi/lo ----
    #pragma unroll
    for (int p = 0; p < 2; p++) {
        // 32 rows x 1024 B, linear into [OFF_K, OFF_K+32K)
        #pragma unroll
        for (int it = 0; it < 16; it++) {
            int idx = tid + it * NT;          // 16B unit
            int r = idx >> 6, c = idx & 63;
            CPASYNC16(sb + OFF_K + r * 1024 + c * 16,
                      qsrc + (size_t)(32 * p + r) * D_ + c * 4);
        }
        CPCOMMIT();
        CPWAIT0();
        __syncthreads();
        // convert: each hi-unit (r,u) = 8 floats -> 16B hi + 16B lo
        #pragma unroll
        for (int it = 0; it < 8; it++) {
            int idx = tid + it * NT;          // 1024 hi-units per pass
            int rl = idx >> 5, u = idx & 31;
            int r = 32 * p + rl;
            float4 f0 = *(const float4*)(smem + OFF_K + rl * 1024 + u * 32);
            float4 f1 = *(const float4*)(smem + OFF_K + rl * 1024 + u * 32 + 16);
            __half2 h01 = __floats2half2_rn(f0.x, f0.y);
            __half2 h23 = __floats2half2_rn(f0.z, f0.w);
            __half2 h45 = __floats2half2_rn(f1.x, f1.y);
            __half2 h67 = __floats2half2_rn(f1.z, f1.w);
            float2 g01 = __half22float2(h01), g23 = __half22float2(h23);
            float2 g45 = __half22float2(h45), g67 = __half22float2(h67);
            __half2 l01 = __floats2half2_rn(f0.x - g01.x, f0.y - g01.y);
            __half2 l23 = __floats2half2_rn(f0.z - g23.x, f0.w - g23.y);
            __half2 l45 = __floats2half2_rn(f1.x - g45.x, f1.y - g45.y);
            __half2 l67 = __floats2half2_rn(f1.z - g67.x, f1.w - g67.y);
            uint32_t off = r * ROWQ + ((u ^ (r & 7)) << 4);
            *(uint4*)(smem + off)       = make_uint4(*(uint32_t*)&h01, *(uint32_t*)&h23,
                                                     *(uint32_t*)&h45, *(uint32_t*)&h67);
            *(uint4*)(smem + off + QSP) = make_uint4(*(uint32_t*)&l01, *(uint32_t*)&l23,
                                                     *(uint32_t*)&l45, *(uint32_t*)&l67);
        }
        __syncthreads();
    }

    // ---- issue K(0) ----
    #pragma unroll
    for (int it = 0; it < 8; it++) {
        int idx = tid + it * NT;              // 1024 units per split
        int r = idx >> 5, u = idx & 31;
        uint32_t d0 = sb + OFF_K + r * ROWQ + ((u ^ (r & 7)) << 4);
        CPASYNC16(d0,       kh_b + (size_t)r * D_ + u * 8);
        CPASYNC16(d0 + KSP, kl_b + (size_t)r * D_ + u * 8);
    }
    CPCOMMIT();

    // ---- ldmatrix lane geometry + swizzle base tables ----
    const int mrow = lane & 7;
    const int rowA = warp * 16 + mrow + (((lane >> 3) & 1) << 3);
    const int hiA  = lane >> 4;
    const int rowB = mrow + ((lane >> 4) << 3);
    const int cB   = (lane >> 3) & 1;

    uint32_t aQh[4], aQl[4], aKh[4], aKl[4], aVh[2];
    #pragma unroll
    for (int m = 0; m < 4; m++) {
        uint32_t swA = (uint32_t)(((2 * m + hiA) ^ mrow) << 4);
        uint32_t swB = (uint32_t)(((2 * m + cB)  ^ mrow) << 4);
        aQh[m] = sb + rowA * ROWQ + swA;
        aQl[m] = aQh[m] + QSP;
        aKh[m] = sb + OFF_K + rowB * ROWQ + swB;
        aKl[m] = aKh[m] + KSP;
    }
    #pragma unroll
    for (int kk = 0; kk < 2; kk++) {
        uint32_t u = 2 * kk + cB;
        aVh[kk] = sb + OFF_V + rowB * ROWV + ((u ^ ((rowB >> 1) & 3)) << 4);
    }

    float O[32][4];
    #pragma unroll
    for (int i = 0; i < 32; i++) { O[i][0] = O[i][1] = O[i][2] = O[i][3] = 0.f; }
    float mr0 = -INFINITY, mr1 = -INFINITY, lr0 = 0.f, lr1 = 0.f;

    const int* mb = mask + (size_t)b * S_;
    const int c2 = (lane & 3) * 2;
    const int g  = lane >> 2;

    for (int jt = 0; jt < 64; jt++) {
        const int kt = jt * 32;

        CPWAIT0();             // K(jt) ready
        __syncthreads();       // all warps done GEMM2(jt-1) -> V buffer free

        // ---- issue V(jt) (overlaps GEMM1): 256 dv rows x 4 units ----
        #pragma unroll
        for (int it = 0; it < 8; it++) {
            int idx = tid + it * NT;
            int r = idx >> 2, u = idx & 3;
            uint32_t d0 = sb + OFF_V + r * ROWV + ((u ^ ((r >> 1) & 3)) << 4);
            CPASYNC16(d0, vh_b + (size_t)r * S_ + kt + u * 8);
        }
        CPCOMMIT();

        // ---- GEMM1: S[16x32] = Qhi*Khi + Qlo*Khi + Qhi*Klo ----
        float s[4][4];
        #pragma unroll
        for (int i = 0; i < 4; i++) s[i][0] = s[i][1] = s[i][2] = s[i][3] = 0.f;

        #pragma unroll
        for (int kk = 0; kk < 16; kk++) {
            const int ko = (kk >> 2) * 128;
            const int m  = kk & 3;
            uint32_t ah[4], al[4];
            LDSM4(ah, aQh[m] + ko);
            LDSM4(al, aQl[m] + ko);
            #pragma unroll
            for (int nn = 0; nn < 2; nn++) {
                uint32_t bh[4], bl[4];
                LDSM4(bh, aKh[m] + nn * (16 * ROWQ) + ko);
                LDSM4(bl, aKl[m] + nn * (16 * ROWQ) + ko);
                MMA(s[2*nn],   ah, bh[0], bh[1]);
                MMA(s[2*nn],   al, bh[0], bh[1]);
                MMA(s[2*nn],   ah, bl[0], bl[1]);
                MMA(s[2*nn+1], ah, bh[2], bh[3]);
                MMA(s[2*nn+1], al, bh[2], bh[3]);
                MMA(s[2*nn+1], ah, bl[2], bl[3]);
            }
        }

        // ---- mask + online softmax ----
        uint32_t Ph[4][2];
        {
            #pragma unroll
            for (int nf = 0; nf < 4; nf++) {
                int2 mv = *(const int2*)(mb + kt + nf * 8 + c2);
                if (mv.x == 0) { s[nf][0] = -1.0e9f; s[nf][2] = -1.0e9f; }
                if (mv.y == 0) { s[nf][1] = -1.0e9f; s[nf][3] = -1.0e9f; }
            }
            float m0 = -INFINITY, m1 = -INFINITY;
            #pragma unroll
            for (int nf = 0; nf < 4; nf++) {
                m0 = fmaxf(m0, fmaxf(s[nf][0], s[nf][1]));
                m1 = fmaxf(m1, fmaxf(s[nf][2], s[nf][3]));
            }
            m0 = fmaxf(m0, __shfl_xor_sync(0xffffffffu, m0, 1));
            m0 = fmaxf(m0, __shfl_xor_sync(0xffffffffu, m0, 2));
            m1 = fmaxf(m1, __shfl_xor_sync(0xffffffffu, m1, 1));
            m1 = fmaxf(m1, __shfl_xor_sync(0xffffffffu, m1, 2));

            float mn0 = fmaxf(mr0, m0), mn1 = fmaxf(mr1, m1);
            float sc0 = exp2p((mr0 - mn0) * LOG2E);
            float sc1 = exp2p((mr1 - mn1) * LOG2E);
            mr0 = mn0; mr1 = mn1;
            float nb0 = -mn0 * LOG2E, nb1 = -mn1 * LOG2E;
            float rs0 = 0.f, rs1 = 0.f;

            #pragma unroll
            for (int nf = 0; nf < 4; nf++) {
                float p0 = exp2p(fmaf(s[nf][0], LOG2E, nb0));
                float p1 = exp2p(fmaf(s[nf][1], LOG2E, nb0));
                float p2 = exp2p(fmaf(s[nf][2], LOG2E, nb1));
                float p3 = exp2p(fmaf(s[nf][3], LOG2E, nb1));
                rs0 += p0 + p1;
                rs1 += p2 + p3;
                PACKH2(Ph[nf][0], p0, p1);
                PACKH2(Ph[nf][1], p2, p3);
            }
            lr0 = lr0 * sc0 + rs0;
            lr1 = lr1 * sc1 + rs1;

            if (__any_sync(0xffffffffu, (sc0 != 1.0f) || (sc1 != 1.0f))) {
                #pragma unroll
                for (int i = 0; i < 32; i++) {
                    O[i][0] *= sc0; O[i][1] *= sc0;
                    O[i][2] *= sc1; O[i][3] *= sc1;
                }
            }
        }

        CPWAIT0();             // V(jt) ready
        __syncthreads();       // all warps done GEMM1 -> K buffer free

        // ---- issue K(jt+1) (overlaps GEMM2) ----
        if (jt + 1 < 64) {
            const __half* khs = kh_b + (size_t)(kt + 32) * D_;
            const __half* kls = kl_b + (size_t)(kt + 32) * D_;
            #pragma unroll
            for (int it = 0; it < 8; it++) {
                int idx = tid + it * NT;
                int r = idx >> 5, u = idx & 31;
                uint32_t d0 = sb + OFF_K + r * ROWQ + ((u ^ (r & 7)) << 4);
                CPASYNC16(d0,       khs + (size_t)r * D_ + u * 8);
                CPASYNC16(d0 + KSP, kls + (size_t)r * D_ + u * 8);
            }
            CPCOMMIT();
        }

        // ---- GEMM2: O += P * Vhi ----
        #pragma unroll
        for (int kk = 0; kk < 2; kk++) {
            uint32_t ah[4] = { Ph[2*kk][0], Ph[2*kk][1], Ph[2*kk+1][0], Ph[2*kk+1][1] };
            #pragma unroll
            for (int nn = 0; nn < 16; nn++) {
                uint32_t bh[4];
                LDSM4(bh, aVh[kk] + nn * (16 * ROWV));
                MMA(O[2*nn],   ah, bh[0], bh[1]);
                MMA(O[2*nn+1], ah, bh[2], bh[3]);
            }
        }
    }

    // ---- epilogue ----
    lr0 += __shfl_xor_sync(0xffffffffu, lr0, 1);
    lr0 += __shfl_xor_sync(0xffffffffu, lr0, 2);
    lr1 += __shfl_xor_sync(0xffffffffu, lr1, 1);
    lr1 += __shfl_xor_sync(0xffffffffu, lr1, 2);
    float inv0 = 1.f / (lr0 * 16.0f);
    float inv1 = 1.f / (lr1 * 16.0f);

    float* ob = out + (size_t)b * D_ * S_;
    const int qg = q0 + warp * 16 + g;
    #pragma unroll
    for (int nn = 0; nn < 32; nn++) {
        int dv = nn * 8 + c2;
        ob[(size_t)dv * S_ + qg]           = O[nn][0] * inv0;
        ob[(size_t)(dv + 1) * S_ + qg]     = O[nn][1] * inv0;
        ob[(size_t)dv * S_ + qg + 8]       = O[nn][2] * inv1;
        ob[(size_t)(dv + 1) * S_ + qg + 8] = O[nn][3] * inv1;
    }
}

// ================= launcher =================
extern "C" void kernel_launch(void* const* d_in, const int* in_sizes, int n_in,
                              void* d_out, int out_size)
{
    (void)in_sizes; (void)n_in; (void)out_size;
    const float* q    = (const float*)d_in[0];
    const float* k    = (const float*)d_in[1];
    const float* v    = (const float*)d_in[2];
    const int*   mask = (const int*)d_in[3];
    float* out = (float*)d_out;

    transpose_split_kernel<<<dim3(S_ / 32, D_ / 32, B_), dim3(32, 8)>>>(k, D_, S_, 0);
    transpose_split_kernel<<<dim3(D_ / 32, S_ / 32, B_), dim3(32, 8)>>>(v, S_, D_, 1);

    cudaFuncSetAttribute(attn_hmma, cudaFuncAttributeMaxDynamicSharedMemorySize, SMEM_SZ);
    attn_hmma<<<dim3(S_ / 64, B_), NT, SMEM_SZ>>>(q, mask, out);
}

// round 10
// speedup vs baseline: 1.0438x; 1.0438x over previous
#include <cuda_runtime.h>
#include <cuda_fp16.h>
#include <math.h>
#include <stdint.h>

#define B_ 16
#define S_ 2048
#define D_ 256
#define NT 256
#define LOG2E 1.4426950408889634f

// ================= fp16 hi/lo split scratch (native layouts) =================
__device__ __half g_Khi[(size_t)B_*D_*S_];   // [b][d][j]  (k native)
__device__ __half g_Klo[(size_t)B_*D_*S_];
__device__ __half g_Vhi[(size_t)B_*S_*D_];   // [b][j][dv] (v native)

__device__ __forceinline__ uint32_t smem_u32(const void* p) {
    uint32_t a;
    asm("{ .reg .u64 t; cvta.to.shared.u64 t, %1; cvt.u32.u64 %0, t; }" : "=r"(a) : "l"(p));
    return a;
}

// fast exp2 on fma/alu pipes (no MUFU)
__device__ __forceinline__ float exp2p(float y) {
    y = fmaxf(y, -125.f);
    float z = __fadd_rn(y, 12582912.f);
    int   n = __float_as_int(z) - 0x4B400000;
    float f = __fsub_rn(y, __fadd_rn(z, -12582912.f));
    float p = 1.33335581e-3f;
    p = fmaf(p, f, 9.61812910e-3f);
    p = fmaf(p, f, 5.55041087e-2f);
    p = fmaf(p, f, 2.40226512e-1f);
    p = fmaf(p, f, 6.93147182e-1f);
    p = fmaf(p, f, 1.0f);
    return __int_as_float(__float_as_int(p) + (n << 23));
}

#define LDSM4(r, a) \
    asm volatile("ldmatrix.sync.aligned.m8n8.x4.shared.b16 {%0,%1,%2,%3}, [%4];" \
        : "=r"((r)[0]), "=r"((r)[1]), "=r"((r)[2]), "=r"((r)[3]) : "r"(a))

#define LDSM4T(r, a) \
    asm volatile("ldmatrix.sync.aligned.m8n8.x4.trans.shared.b16 {%0,%1,%2,%3}, [%4];" \
        : "=r"((r)[0]), "=r"((r)[1]), "=r"((r)[2]), "=r"((r)[3]) : "r"(a))

#define MMA(d, a, b0, b1) \
    asm volatile("mma.sync.aligned.m16n8k16.row.col.f32.f16.f16.f32 " \
        "{%0,%1,%2,%3},{%4,%5,%6,%7},{%8,%9},{%0,%1,%2,%3};" \
        : "+f"((d)[0]), "+f"((d)[1]), "+f"((d)[2]), "+f"((d)[3]) \
        : "r"((a)[0]), "r"((a)[1]), "r"((a)[2]), "r"((a)[3]), "r"(b0), "r"(b1))

#define PACKH2(d, lo, hi) \
    asm("cvt.rn.f16x2.f32 %0, %1, %2;" : "=r"(d) : "f"(hi), "f"(lo))

#define CPASYNC16(dst, src) \
    asm volatile("cp.async.cg.shared.global [%0], [%1], 16;" :: "r"(dst), "l"(src))
#define CPCOMMIT()   asm volatile("cp.async.commit_group;" ::: "memory")
#define CPWAIT_ALL() asm volatile("cp.async.wait_group 0;" ::: "memory")
#define CPWAIT_1()   asm volatile("cp.async.wait_group 1;" ::: "memory")

// ================= prep kernels: coalesced elementwise splits =================
__global__ void split_k_kernel(const float* __restrict__ k) {
    size_t i = ((size_t)blockIdx.x * blockDim.x + threadIdx.x) * 4;
    float4 f = *(const float4*)(k + i);
    __half2 h0 = __floats2half2_rn(f.x, f.y);
    __half2 h1 = __floats2half2_rn(f.z, f.w);
    float2 g0 = __half22float2(h0), g1 = __half22float2(h1);
    __half2 l0 = __floats2half2_rn(f.x - g0.x, f.y - g0.y);
    __half2 l1 = __floats2half2_rn(f.z - g1.x, f.w - g1.y);
    *(__half2*)(g_Khi + i)     = h0;
    *(__half2*)(g_Khi + i + 2) = h1;
    *(__half2*)(g_Klo + i)     = l0;
    *(__half2*)(g_Klo + i + 2) = l1;
}
__global__ void split_v_kernel(const float* __restrict__ v) {
    size_t i = ((size_t)blockIdx.x * blockDim.x + threadIdx.x) * 4;
    float4 f = *(const float4*)(v + i);
    *(__half2*)(g_Vhi + i)     = __floats2half2_rn(f.x, f.y);
    *(__half2*)(g_Vhi + i + 2) = __floats2half2_rn(f.z, f.w);
}

// ================= main kernel =================
// Q: [128 q][256 d] hi/lo, rows 512B, swizzle (u^(r&7))<<4          (128 KB)
// K: [256 d][32 j]  hi/lo x2 bufs, rows 64B, swizzle (u^((r>>1)&3)) ( 64 KB)
// V: [32 j][256 dv] hi, rows 512B, swizzle low3(u)^(r&7)            ( 16 KB)
#define QSP    65536
#define OFF_K  131072
#define KBUF   32768
#define KSP    16384
#define OFF_V  196608
#define SMEM_SZ 212992

__global__ void __launch_bounds__(NT, 1)
attn_hmma(const float* __restrict__ qf,
          const int* __restrict__ mask, float* __restrict__ out)
{
    extern __shared__ char smem[];
    const uint32_t sb = smem_u32(smem);
    const int tid  = threadIdx.x;
    const int lane = tid & 31;
    const int warp = tid >> 5;
    const int b    = blockIdx.y;
    const int q0   = blockIdx.x * 128;

    const __half* khb = g_Khi + (size_t)b * D_ * S_;
    const __half* klb = g_Klo + (size_t)b * D_ * S_;
    const __half* vhb = g_Vhi + (size_t)b * S_ * D_;
    const float*  qsrc = qf + ((size_t)b * S_ + q0) * D_;

    // ---- prologue: Q fp32 -> hi/lo via K region as staging (2 passes x 64 rows) ----
    #pragma unroll
    for (int p = 0; p < 2; p++) {
        #pragma unroll
        for (int it = 0; it < 16; it++) {
            int idx = tid + it * NT;          // 4096 16B-units
            int r = idx >> 6, c = idx & 63;
            CPASYNC16(sb + OFF_K + r * 1024 + c * 16,
                      qsrc + (size_t)(64 * p + r) * D_ + c * 4);
        }
        CPCOMMIT();
        CPWAIT_ALL();
        __syncthreads();
        #pragma unroll
        for (int it = 0; it < 8; it++) {
            int idx = tid + it * NT;          // 2048 hi-units
            int rl = idx >> 5, u = idx & 31;
            int r = 64 * p + rl;
            float4 f0 = *(const float4*)(smem + OFF_K + rl * 1024 + u * 32);
            float4 f1 = *(const float4*)(smem + OFF_K + rl * 1024 + u * 32 + 16);
            __half2 h01 = __floats2half2_rn(f0.x, f0.y);
            __half2 h23 = __floats2half2_rn(f0.z, f0.w);
            __half2 h45 = __floats2half2_rn(f1.x, f1.y);
            __half2 h67 = __floats2half2_rn(f1.z, f1.w);
            float2 g01 = __half22float2(h01), g23 = __half22float2(h23);
            float2 g45 = __half22float2(h45), g67 = __half22float2(h67);
            __half2 l01 = __floats2half2_rn(f0.x - g01.x, f0.y - g01.y);
            __half2 l23 = __floats2half2_rn(f0.z - g23.x, f0.w - g23.y);
            __half2 l45 = __floats2half2_rn(f1.x - g45.x, f1.y - g45.y);
            __half2 l67 = __floats2half2_rn(f1.z - g67.x, f1.w - g67.y);
            uint32_t off = r * 512 + ((u ^ (r & 7)) << 4);
            *(uint4*)(smem + off)       = make_uint4(*(uint32_t*)&h01, *(uint32_t*)&h23,
                                                     *(uint32_t*)&h45, *(uint32_t*)&h67);
            *(uint4*)(smem + off + QSP) = make_uint4(*(uint32_t*)&l01, *(uint32_t*)&l23,
                                                     *(uint32_t*)&l45, *(uint32_t*)&l67);
        }
        __syncthreads();
    }

    // ---- issue K(0) into buf 0 ----
    #pragma unroll
    for (int it = 0; it < 4; it++) {
        int idx = tid + it * NT;              // 1024 units per split
        int r = idx >> 2, u = idx & 3;
        uint32_t dst = sb + OFF_K + r * 64 + ((u ^ ((r >> 1) & 3)) << 4);
        CPASYNC16(dst,       khb + (size_t)r * S_ + u * 8);
        CPASYNC16(dst + KSP, klb + (size_t)r * S_ + u * 8);
    }
    CPCOMMIT();

    // ---- lane geometry ----
    const int mrow = lane & 7;
    const int rowA = warp * 16 + mrow + (((lane >> 3) & 1) << 3);
    const int hiA  = lane >> 4;
    const int krb  = ((lane >> 3) & 1) * 8 + (lane & 7);   // k-row within k16
    const int ul   = lane >> 4;                            // n-unit half

    uint32_t aQ[4];
    #pragma unroll
    for (int m = 0; m < 4; m++)
        aQ[m] = sb + rowA * 512 + ((((2 * m + hiA)) ^ mrow) << 4);

    uint32_t kbs[2], vbs[4];
    #pragma unroll
    for (int nh = 0; nh < 2; nh++)
        kbs[nh] = (uint32_t)(krb * 64 + (((nh * 2 + ul) ^ ((krb >> 1) & 3)) << 4));
    #pragma unroll
    for (int i = 0; i < 4; i++)
        vbs[i] = sb + OFF_V + (uint32_t)(krb * 512 + (((i * 2 + ul) ^ (krb & 7)) << 4));

    float O[32][4];
    #pragma unroll
    for (int i = 0; i < 32; i++) { O[i][0] = O[i][1] = O[i][2] = O[i][3] = 0.f; }
    float mr0 = -INFINITY, mr1 = -INFINITY, lr0 = 0.f, lr1 = 0.f;

    const int* mb = mask + (size_t)b * S_;
    const int c2 = (lane & 3) * 2;
    const int g  = lane >> 2;

    for (int jt = 0; jt < 64; jt++) {
        const int kt = jt * 32;
        const int p  = jt & 1;
        const uint32_t kbB = sb + OFF_K + (uint32_t)p * KBUF;

        CPWAIT_ALL();          // K(jt) complete (this warp's groups)
        __syncthreads();       // visible to all; GEMM2(jt-1) done by all

        // ---- issue V(jt) (group A) ----
        #pragma unroll
        for (int it = 0; it < 4; it++) {
            int idx = tid + it * NT;          // 1024 units
            int r = idx >> 5, u = idx & 31;
            uint32_t dst = sb + OFF_V + r * 512 + ((u >> 3) << 7)
                         + (((u & 7) ^ (r & 7)) << 4);
            CPASYNC16(dst, vhb + (size_t)(kt + r) * D_ + u * 8);
        }
        CPCOMMIT();
        // ---- issue K(jt+1) into buf p^1 (group B; wraps harmlessly on last) ----
        {
            const int ktn = ((jt + 1) & 63) * 32;
            const uint32_t kbN = sb + OFF_K + (uint32_t)(p ^ 1) * KBUF;
            #pragma unroll
            for (int it = 0; it < 4; it++) {
                int idx = tid + it * NT;
                int r = idx >> 2, u = idx & 3;
                uint32_t dst = kbN + r * 64 + ((u ^ ((r >> 1) & 3)) << 4);
                CPASYNC16(dst,       khb + (size_t)r * S_ + ktn + u * 8);
                CPASYNC16(dst + KSP, klb + (size_t)r * S_ + ktn + u * 8);
            }
            CPCOMMIT();
        }

        // mask (preload)
        int2 mv[4];
        #pragma unroll
        for (int nf = 0; nf < 4; nf++)
            mv[nf] = *(const int2*)(mb + kt + nf * 8 + c2);

        // ---- GEMM1: S[16x32] = Qhi*Khi + Qlo*Khi + Qhi*Klo ----
        float s[4][4];
        #pragma unroll
        for (int i = 0; i < 4; i++) s[i][0] = s[i][1] = s[i][2] = s[i][3] = 0.f;

        const uint32_t kb0 = kbB + kbs[0];
        const uint32_t kb1 = kbB + kbs[1];
        #pragma unroll
        for (int kk = 0; kk < 16; kk++) {
            uint32_t ah[4], al[4], bh[4], bl[4], bh2[4], bl2[4];
            LDSM4(ah, aQ[kk & 3] + (kk >> 2) * 128);
            LDSM4(al, aQ[kk & 3] + (kk >> 2) * 128 + QSP);
            LDSM4T(bh,  kb0 + kk * 1024);
            LDSM4T(bl,  kb0 + kk * 1024 + KSP);
            LDSM4T(bh2, kb1 + kk * 1024);
            LDSM4T(bl2, kb1 + kk * 1024 + KSP);
            MMA(s[0], ah, bh[0], bh[1]);
            MMA(s[0], al, bh[0], bh[1]);
            MMA(s[0], ah, bl[0], bl[1]);
            MMA(s[1], ah, bh[2], bh[3]);
            MMA(s[1], al, bh[2], bh[3]);
            MMA(s[1], ah, bl[2], bl[3]);
            MMA(s[2], ah, bh2[0], bh2[1]);
            MMA(s[2], al, bh2[0], bh2[1]);
            MMA(s[2], ah, bl2[0], bl2[1]);
            MMA(s[3], ah, bh2[2], bh2[3]);
            MMA(s[3], al, bh2[2], bh2[3]);
            MMA(s[3], ah, bl2[2], bl2[3]);
        }

        // ---- mask + online softmax ----
        uint32_t Ph[4][2];
        {
            #pragma unroll
            for (int nf = 0; nf < 4; nf++) {
                if (mv[nf].x == 0) { s[nf][0] = -1.0e9f; s[nf][2] = -1.0e9f; }
                if (mv[nf].y == 0) { s[nf][1] = -1.0e9f; s[nf][3] = -1.0e9f; }
            }
            float m0 = -INFINITY, m1 = -INFINITY;
            #pragma unroll
            for (int nf = 0; nf < 4; nf++) {
                m0 = fmaxf(m0, fmaxf(s[nf][0], s[nf][1]));
                m1 = fmaxf(m1, fmaxf(s[nf][2], s[nf][3]));
            }
            m0 = fmaxf(m0, __shfl_xor_sync(0xffffffffu, m0, 1));
            m0 = fmaxf(m0, __shfl_xor_sync(0xffffffffu, m0, 2));
            m1 = fmaxf(m1, __shfl_xor_sync(0xffffffffu, m1, 1));
            m1 = fmaxf(m1, __shfl_xor_sync(0xffffffffu, m1, 2));

            float mn0 = fmaxf(mr0, m0), mn1 = fmaxf(mr1, m1);
            float sc0 = exp2p((mr0 - mn0) * LOG2E);
            float sc1 = exp2p((mr1 - mn1) * LOG2E);
            mr0 = mn0; mr1 = mn1;
            float nb0 = -mn0 * LOG2E, nb1 = -mn1 * LOG2E;
            float rs0 = 0.f, rs1 = 0.f;

            #pragma unroll
            for (int nf = 0; nf < 4; nf++) {
                float p0 = exp2p(fmaf(s[nf][0], LOG2E, nb0));
                float p1 = exp2p(fmaf(s[nf][1], LOG2E, nb0));
                float p2 = exp2p(fmaf(s[nf][2], LOG2E, nb1));
                float p3 = exp2p(fmaf(s[nf][3], LOG2E, nb1));
                rs0 += p0 + p1;
                rs1 += p2 + p3;
                PACKH2(Ph[nf][0], p0, p1);
                PACKH2(Ph[nf][1], p2, p3);
            }
            lr0 = lr0 * sc0 + rs0;
            lr1 = lr1 * sc1 + rs1;

            if (__any_sync(0xffffffffu, (sc0 != 1.0f) || (sc1 != 1.0f))) {
                #pragma unroll
                for (int i = 0; i < 32; i++) {
                    O[i][0] *= sc0; O[i][1] *= sc0;
                    O[i][2] *= sc1; O[i][3] *= sc1;
                }
            }
        }

        CPWAIT_1();            // V(jt) complete (K(jt+1) still pending)
        __syncthreads();       // V visible to all

        // ---- GEMM2: O += P * Vhi ----
        #pragma unroll
        for (int kk = 0; kk < 2; kk++) {
            uint32_t ah[4] = { Ph[2*kk][0], Ph[2*kk][1], Ph[2*kk+1][0], Ph[2*kk+1][1] };
            #pragma unroll
            for (int nn = 0; nn < 16; nn++) {
                uint32_t bh[4];
                LDSM4T(bh, vbs[nn & 3] + ((nn >> 2) << 7) + kk * 8192);
                MMA(O[2*nn],   ah, bh[0], bh[1]);
                MMA(O[2*nn+1], ah, bh[2], bh[3]);
            }
        }
    }
    CPWAIT_ALL();

    // ---- epilogue ----
    lr0 += __shfl_xor_sync(0xffffffffu, lr0, 1);
    lr0 += __shfl_xor_sync(0xffffffffu, lr0, 2);
    lr1 += __shfl_xor_sync(0xffffffffu, lr1, 1);
    lr1 += __shfl_xor_sync(0xffffffffu, lr1, 2);
    float inv0 = 1.f / (lr0 * 16.0f);
    float inv1 = 1.f / (lr1 * 16.0f);

    float* ob = out + (size_t)b * D_ * S_;
    const int qg = q0 + warp * 16 + g;
    #pragma unroll
    for (int nn = 0; nn < 32; nn++) {
        int dv = nn * 8 + c2;
        ob[(size_t)dv * S_ + qg]           = O[nn][0] * inv0;
        ob[(size_t)(dv + 1) * S_ + qg]     = O[nn][1] * inv0;
        ob[(size_t)dv * S_ + qg + 8]       = O[nn][2] * inv1;
        ob[(size_t)(dv + 1) * S_ + qg + 8] = O[nn][3] * inv1;
    }
}

// ================= launcher =================
extern "C" void kernel_launch(void* const* d_in, const int* in_sizes, int n_in,
                              void* d_out, int out_size)
{
    (void)in_sizes; (void)n_in; (void)out_size;
    const float* q    = (const float*)d_in[0];
    const float* k    = (const float*)d_in[1];
    const float* v    = (const float*)d_in[2];
    const int*   mask = (const int*)d_in[3];
    float* out = (float*)d_out;

    const int nblk = (B_ * D_ * S_) / 4 / 256;
    split_k_kernel<<<nblk, 256>>>(k);
    split_v_kernel<<<nblk, 256>>>(v);

    cudaFuncSetAttribute(attn_hmma, cudaFuncAttributeMaxDynamicSharedMemorySize, SMEM_SZ);
    attn_hmma<<<dim3(S_ / 128, B_), NT, SMEM_SZ>>>(q, mask, out);
}

// round 11
// speedup vs baseline: 1.0632x; 1.0185x over previous
#include <cuda_runtime.h>
#include <cuda_fp16.h>
#include <math.h>
#include <stdint.h>

#define B_ 16
#define S_ 2048
#define D_ 256
#define NT 256
#define LOG2E 1.4426950408889634f

// ================= fp16 hi/lo split scratch (native layouts) =================
__device__ __half g_Khi[(size_t)B_*D_*S_];   // [b][d][j]  (k native)
__device__ __half g_Klo[(size_t)B_*D_*S_];
__device__ __half g_Vhi[(size_t)B_*S_*D_];   // [b][j][dv] (v native)

__device__ __forceinline__ uint32_t smem_u32(const void* p) {
    uint32_t a;
    asm("{ .reg .u64 t; cvta.to.shared.u64 t, %1; cvt.u32.u64 %0, t; }" : "=r"(a) : "l"(p));
    return a;
}

// fast exp2 on fma/alu pipes (no MUFU)
__device__ __forceinline__ float exp2p(float y) {
    y = fmaxf(y, -125.f);
    float z = __fadd_rn(y, 12582912.f);
    int   n = __float_as_int(z) - 0x4B400000;
    float f = __fsub_rn(y, __fadd_rn(z, -12582912.f));
    float p = 1.33335581e-3f;
    p = fmaf(p, f, 9.61812910e-3f);
    p = fmaf(p, f, 5.55041087e-2f);
    p = fmaf(p, f, 2.40226512e-1f);
    p = fmaf(p, f, 6.93147182e-1f);
    p = fmaf(p, f, 1.0f);
    return __int_as_float(__float_as_int(p) + (n << 23));
}

#define LDSM4(r, a) \
    asm volatile("ldmatrix.sync.aligned.m8n8.x4.shared.b16 {%0,%1,%2,%3}, [%4];" \
        : "=r"((r)[0]), "=r"((r)[1]), "=r"((r)[2]), "=r"((r)[3]) : "r"(a))

#define LDSM4T(r, a) \
    asm volatile("ldmatrix.sync.aligned.m8n8.x4.trans.shared.b16 {%0,%1,%2,%3}, [%4];" \
        : "=r"((r)[0]), "=r"((r)[1]), "=r"((r)[2]), "=r"((r)[3]) : "r"(a))

#define MMA(d, a, b0, b1) \
    asm volatile("mma.sync.aligned.m16n8k16.row.col.f32.f16.f16.f32 " \
        "{%0,%1,%2,%3},{%4,%5,%6,%7},{%8,%9},{%0,%1,%2,%3};" \
        : "+f"((d)[0]), "+f"((d)[1]), "+f"((d)[2]), "+f"((d)[3]) \
        : "r"((a)[0]), "r"((a)[1]), "r"((a)[2]), "r"((a)[3]), "r"(b0), "r"(b1))

#define PACKH2(d, lo, hi) \
    asm("cvt.rn.f16x2.f32 %0, %1, %2;" : "=r"(d) : "f"(hi), "f"(lo))

#define CPASYNC16(dst, src) \
    asm volatile("cp.async.cg.shared.global [%0], [%1], 16;" :: "r"(dst), "l"(src))
#define CPCOMMIT()   asm volatile("cp.async.commit_group;" ::: "memory")
#define CPWAIT_ALL() asm volatile("cp.async.wait_group 0;" ::: "memory")

// ================= prep kernels: coalesced elementwise splits =================
__global__ void split_k_kernel(const float* __restrict__ k) {
    size_t i = ((size_t)blockIdx.x * blockDim.x + threadIdx.x) * 4;
    float4 f = *(const float4*)(k + i);
    __half2 h0 = __floats2half2_rn(f.x, f.y);
    __half2 h1 = __floats2half2_rn(f.z, f.w);
    float2 g0 = __half22float2(h0), g1 = __half22float2(h1);
    __half2 l0 = __floats2half2_rn(f.x - g0.x, f.y - g0.y);
    __half2 l1 = __floats2half2_rn(f.z - g1.x, f.w - g1.y);
    *(__half2*)(g_Khi + i)     = h0;
    *(__half2*)(g_Khi + i + 2) = h1;
    *(__half2*)(g_Klo + i)     = l0;
    *(__half2*)(g_Klo + i + 2) = l1;
}
__global__ void split_v_kernel(const float* __restrict__ v) {
    size_t i = ((size_t)blockIdx.x * blockDim.x + threadIdx.x) * 4;
    float4 f = *(const float4*)(v + i);
    *(__half2*)(g_Vhi + i)     = __floats2half2_rn(f.x, f.y);
    *(__half2*)(g_Vhi + i + 2) = __floats2half2_rn(f.z, f.w);
}

// ================= main kernel =================
// Q: [128 q][256 d] hi/lo, rows 512B                               (128 KB)
// K: [256 d][32 j]  hi/lo, rows 64B, x2 bufs                       ( 64 KB)
// V: [32 j][256 dv] hi, rows 512B, x2 bufs                         ( 32 KB)
#define QSP    65536
#define OFF_K  131072
#define KBUF   32768
#define KSP    16384
#define OFF_V  196608
#define VBUF   16384
#define SMEM_SZ 229376

__global__ void __launch_bounds__(NT, 1)
attn_hmma(const float* __restrict__ qf,
          const int* __restrict__ mask, float* __restrict__ out)
{
    extern __shared__ char smem[];
    const uint32_t sb = smem_u32(smem);
    const int tid  = threadIdx.x;
    const int lane = tid & 31;
    const int warp = tid >> 5;
    const int b    = blockIdx.y;
    const int q0   = blockIdx.x * 128;

    const __half* khb = g_Khi + (size_t)b * D_ * S_;
    const __half* klb = g_Klo + (size_t)b * D_ * S_;
    const __half* vhb = g_Vhi + (size_t)b * S_ * D_;
    const float*  qsrc = qf + ((size_t)b * S_ + q0) * D_;

    // ---- prologue: Q fp32 -> hi/lo via K region as staging (2 passes x 64 rows) ----
    #pragma unroll
    for (int p = 0; p < 2; p++) {
        #pragma unroll
        for (int it = 0; it < 16; it++) {
            int idx = tid + it * NT;
            int r = idx >> 6, c = idx & 63;
            CPASYNC16(sb + OFF_K + r * 1024 + c * 16,
                      qsrc + (size_t)(64 * p + r) * D_ + c * 4);
        }
        CPCOMMIT();
        CPWAIT_ALL();
        __syncthreads();
        #pragma unroll
        for (int it = 0; it < 8; it++) {
            int idx = tid + it * NT;
            int rl = idx >> 5, u = idx & 31;
            int r = 64 * p + rl;
            float4 f0 = *(const float4*)(smem + OFF_K + rl * 1024 + u * 32);
            float4 f1 = *(const float4*)(smem + OFF_K + rl * 1024 + u * 32 + 16);
            __half2 h01 = __floats2half2_rn(f0.x, f0.y);
            __half2 h23 = __floats2half2_rn(f0.z, f0.w);
            __half2 h45 = __floats2half2_rn(f1.x, f1.y);
            __half2 h67 = __floats2half2_rn(f1.z, f1.w);
            float2 g01 = __half22float2(h01), g23 = __half22float2(h23);
            float2 g45 = __half22float2(h45), g67 = __half22float2(h67);
            __half2 l01 = __floats2half2_rn(f0.x - g01.x, f0.y - g01.y);
            __half2 l23 = __floats2half2_rn(f0.z - g23.x, f0.w - g23.y);
            __half2 l45 = __floats2half2_rn(f1.x - g45.x, f1.y - g45.y);
            __half2 l67 = __floats2half2_rn(f1.z - g67.x, f1.w - g67.y);
            uint32_t off = r * 512 + ((u ^ (r & 7)) << 4);
            *(uint4*)(smem + off)       = make_uint4(*(uint32_t*)&h01, *(uint32_t*)&h23,
                                                     *(uint32_t*)&h45, *(uint32_t*)&h67);
            *(uint4*)(smem + off + QSP) = make_uint4(*(uint32_t*)&l01, *(uint32_t*)&l23,
                                                     *(uint32_t*)&l45, *(uint32_t*)&l67);
        }
        __syncthreads();
    }

    // ---- zero V buf 1 (read by the harmless jt=0 GEMM2 with Ph=0) ----
    #pragma unroll
    for (int it = 0; it < 4; it++) {
        int idx = tid + it * NT;
        *(uint4*)(smem + OFF_V + VBUF + idx * 16) = make_uint4(0, 0, 0, 0);
    }

    // ---- issue K(0) into buf 0 ----
    #pragma unroll
    for (int it = 0; it < 4; it++) {
        int idx = tid + it * NT;
        int r = idx >> 2, u = idx & 3;
        uint32_t dst = sb + OFF_K + r * 64 + ((u ^ ((r >> 1) & 3)) << 4);
        CPASYNC16(dst,       khb + (size_t)r * S_ + u * 8);
        CPASYNC16(dst + KSP, klb + (size_t)r * S_ + u * 8);
    }
    CPCOMMIT();

    // ---- lane geometry ----
    const int mrow = lane & 7;
    const int rowA = warp * 16 + mrow + (((lane >> 3) & 1) << 3);
    const int hiA  = lane >> 4;
    const int krb  = ((lane >> 3) & 1) * 8 + (lane & 7);
    const int ul   = lane >> 4;

    uint32_t aQ[4];
    #pragma unroll
    for (int m = 0; m < 4; m++)
        aQ[m] = sb + rowA * 512 + ((((2 * m + hiA)) ^ mrow) << 4);

    uint32_t kbs[2], vrel[4];
    #pragma unroll
    for (int nh = 0; nh < 2; nh++)
        kbs[nh] = (uint32_t)(krb * 64 + (((nh * 2 + ul) ^ ((krb >> 1) & 3)) << 4));
    #pragma unroll
    for (int i = 0; i < 4; i++)
        vrel[i] = (uint32_t)(krb * 512 + (((i * 2 + ul) ^ (krb & 7)) << 4));

    float O[32][4];
    #pragma unroll
    for (int i = 0; i < 32; i++) { O[i][0] = O[i][1] = O[i][2] = O[i][3] = 0.f; }
    float mr0 = -INFINITY, mr1 = -INFINITY, lr0 = 0.f, lr1 = 0.f;
    uint32_t PhP[4][2];
    #pragma unroll
    for (int i = 0; i < 4; i++) { PhP[i][0] = 0u; PhP[i][1] = 0u; }

    const int* mb = mask + (size_t)b * S_;
    const int c2 = (lane & 3) * 2;
    const int g  = lane >> 2;

    for (int jt = 0; jt < 64; jt++) {
        const int kt = jt * 32;
        const int p  = jt & 1;
        const uint32_t kB = sb + OFF_K + (uint32_t)p * KBUF;
        const uint32_t vB = sb + OFF_V + (uint32_t)(p ^ 1) * VBUF;   // V(jt-1)

        CPWAIT_ALL();          // K(jt) + V(jt-1) complete
        __syncthreads();       // all warps past reads of bufs being refilled

        // ---- issue V(jt) -> vbuf p ----
        #pragma unroll
        for (int it = 0; it < 4; it++) {
            int idx = tid + it * NT;
            int r = idx >> 5, u = idx & 31;
            uint32_t dst = sb + OFF_V + (uint32_t)p * VBUF + r * 512
                         + ((u >> 3) << 7) + (((u & 7) ^ (r & 7)) << 4);
            CPASYNC16(dst, vhb + (size_t)(kt + r) * D_ + u * 8);
        }
        CPCOMMIT();
        // ---- issue K(jt+1) -> kbuf p^1 (wraps harmlessly on last) ----
        {
            const int ktn = ((jt + 1) & 63) * 32;
            const uint32_t kbN = sb + OFF_K + (uint32_t)(p ^ 1) * KBUF;
            #pragma unroll
            for (int it = 0; it < 4; it++) {
                int idx = tid + it * NT;
                int r = idx >> 2, u = idx & 3;
                uint32_t dst = kbN + r * 64 + ((u ^ ((r >> 1) & 3)) << 4);
                CPASYNC16(dst,       khb + (size_t)r * S_ + ktn + u * 8);
                CPASYNC16(dst + KSP, klb + (size_t)r * S_ + ktn + u * 8);
            }
            CPCOMMIT();
        }

        int2 mv[4];
        #pragma unroll
        for (int nf = 0; nf < 4; nf++)
            mv[nf] = *(const int2*)(mb + kt + nf * 8 + c2);

        // ---- fused: GEMM1(jt) + GEMM2(jt-1), interleaved in 4 chunks ----
        float s[4][4];
        #pragma unroll
        for (int i = 0; i < 4; i++) s[i][0] = s[i][1] = s[i][2] = s[i][3] = 0.f;

        const uint32_t kb0 = kB + kbs[0];
        const uint32_t kb1 = kB + kbs[1];
        #pragma unroll
        for (int c = 0; c < 4; c++) {
            // GEMM2(jt-1) chunk: kkv = c>>1, nn in [(c&1)*8, +8)
            {
                const int kkv = c >> 1;
                uint32_t ap[4] = { PhP[2*kkv][0], PhP[2*kkv][1],
                                   PhP[2*kkv+1][0], PhP[2*kkv+1][1] };
                #pragma unroll
                for (int n2 = 0; n2 < 8; n2++) {
                    int nn = (c & 1) * 8 + n2;
                    uint32_t bh[4];
                    LDSM4T(bh, vB + vrel[nn & 3] + ((nn >> 2) << 7) + kkv * 8192);
                    MMA(O[2*nn],   ap, bh[0], bh[1]);
                    MMA(O[2*nn+1], ap, bh[2], bh[3]);
                }
            }
            // GEMM1(jt) chunk: kk in [4c, 4c+4)
            #pragma unroll
            for (int k2 = 0; k2 < 4; k2++) {
                const int kk = c * 4 + k2;
                uint32_t ah[4], al[4], bh[4], bl[4], bh2[4], bl2[4];
                LDSM4(ah, aQ[k2] + c * 128);
                LDSM4(al, aQ[k2] + c * 128 + QSP);
                LDSM4T(bh,  kb0 + kk * 1024);
                LDSM4T(bl,  kb0 + kk * 1024 + KSP);
                LDSM4T(bh2, kb1 + kk * 1024);
                LDSM4T(bl2, kb1 + kk * 1024 + KSP);
                MMA(s[0], ah, bh[0], bh[1]);
                MMA(s[0], al, bh[0], bh[1]);
                MMA(s[0], ah, bl[0], bl[1]);
                MMA(s[1], ah, bh[2], bh[3]);
                MMA(s[1], al, bh[2], bh[3]);
                MMA(s[1], ah, bl[2], bl[3]);
                MMA(s[2], ah, bh2[0], bh2[1]);
                MMA(s[2], al, bh2[0], bh2[1]);
                MMA(s[2], ah, bl2[0], bl2[1]);
                MMA(s[3], ah, bh2[2], bh2[3]);
                MMA(s[3], al, bh2[2], bh2[3]);
                MMA(s[3], ah, bl2[2], bl2[3]);
            }
        }

        // ---- mask + online softmax (after GEMM2(jt-1) is in O) ----
        {
            #pragma unroll
            for (int nf = 0; nf < 4; nf++) {
                if (mv[nf].x == 0) { s[nf][0] = -1.0e9f; s[nf][2] = -1.0e9f; }
                if (mv[nf].y == 0) { s[nf][1] = -1.0e9f; s[nf][3] = -1.0e9f; }
            }
            float m0 = -INFINITY, m1 = -INFINITY;
            #pragma unroll
            for (int nf = 0; nf < 4; nf++) {
                m0 = fmaxf(m0, fmaxf(s[nf][0], s[nf][1]));
                m1 = fmaxf(m1, fmaxf(s[nf][2], s[nf][3]));
            }
            m0 = fmaxf(m0, __shfl_xor_sync(0xffffffffu, m0, 1));
            m0 = fmaxf(m0, __shfl_xor_sync(0xffffffffu, m0, 2));
            m1 = fmaxf(m1, __shfl_xor_sync(0xffffffffu, m1, 1));
            m1 = fmaxf(m1, __shfl_xor_sync(0xffffffffu, m1, 2));

            float mn0 = fmaxf(mr0, m0), mn1 = fmaxf(mr1, m1);
            float sc0 = exp2p((mr0 - mn0) * LOG2E);
            float sc1 = exp2p((mr1 - mn1) * LOG2E);
            mr0 = mn0; mr1 = mn1;
            float nb0 = -mn0 * LOG2E, nb1 = -mn1 * LOG2E;
            float rs0 = 0.f, rs1 = 0.f;

            #pragma unroll
            for (int nf = 0; nf < 4; nf++) {
                float p0 = exp2p(fmaf(s[nf][0], LOG2E, nb0));
                float p1 = exp2p(fmaf(s[nf][1], LOG2E, nb0));
                float p2 = exp2p(fmaf(s[nf][2], LOG2E, nb1));
                float p3 = exp2p(fmaf(s[nf][3], LOG2E, nb1));
                rs0 += p0 + p1;
                rs1 += p2 + p3;
                PACKH2(PhP[nf][0], p0, p1);
                PACKH2(PhP[nf][1], p2, p3);
            }
            lr0 = lr0 * sc0 + rs0;
            lr1 = lr1 * sc1 + rs1;

            if (__any_sync(0xffffffffu, (sc0 != 1.0f) || (sc1 != 1.0f))) {
                #pragma unroll
                for (int i = 0; i < 32; i++) {
                    O[i][0] *= sc0; O[i][1] *= sc0;
                    O[i][2] *= sc1; O[i][3] *= sc1;
                }
            }
        }
    }

    // ---- peeled GEMM2(63): V(63) in vbuf 1 ----
    CPWAIT_ALL();
    __syncthreads();
    {
        const uint32_t vB = sb + OFF_V + VBUF;
        #pragma unroll
        for (int kk = 0; kk < 2; kk++) {
            uint32_t ap[4] = { PhP[2*kk][0], PhP[2*kk][1], PhP[2*kk+1][0], PhP[2*kk+1][1] };
            #pragma unroll
            for (int nn = 0; nn < 16; nn++) {
                uint32_t bh[4];
                LDSM4T(bh, vB + vrel[nn & 3] + ((nn >> 2) << 7) + kk * 8192);
                MMA(O[2*nn],   ap, bh[0], bh[1]);
                MMA(O[2*nn+1], ap, bh[2], bh[3]);
            }
        }
    }

    // ---- epilogue ----
    lr0 += __shfl_xor_sync(0xffffffffu, lr0, 1);
    lr0 += __shfl_xor_sync(0xffffffffu, lr0, 2);
    lr1 += __shfl_xor_sync(0xffffffffu, lr1, 1);
    lr1 += __shfl_xor_sync(0xffffffffu, lr1, 2);
    float inv0 = 1.f / (lr0 * 16.0f);
    float inv1 = 1.f / (lr1 * 16.0f);

    float* ob = out + (size_t)b * D_ * S_;
    const int qg = q0 + warp * 16 + g;
    #pragma unroll
    for (int nn = 0; nn < 32; nn++) {
        int dv = nn * 8 + c2;
        ob[(size_t)dv * S_ + qg]           = O[nn][0] * inv0;
        ob[(size_t)(dv + 1) * S_ + qg]     = O[nn][1] * inv0;
        ob[(size_t)dv * S_ + qg + 8]       = O[nn][2] * inv1;
        ob[(size_t)(dv + 1) * S_ + qg + 8] = O[nn][3] * inv1;
    }
}

// ================= launcher =================
extern "C" void kernel_launch(void* const* d_in, const int* in_sizes, int n_in,
                              void* d_out, int out_size)
{
    (void)in_sizes; (void)n_in; (void)out_size;
    const float* q    = (const float*)d_in[0];
    const float* k    = (const float*)d_in[1];
    const float* v    = (const float*)d_in[2];
    const int*   mask = (const int*)d_in[3];
    float* out = (float*)d_out;

    const int nblk = (B_ * D_ * S_) / 4 / 256;
    split_k_kernel<<<nblk, 256>>>(k);
    split_v_kernel<<<nblk, 256>>>(v);

    cudaFuncSetAttribute(attn_hmma, cudaFuncAttributeMaxDynamicSharedMemorySize, SMEM_SZ);
    attn_hmma<<<dim3(S_ / 128, B_), NT, SMEM_SZ>>>(q, mask, out);
}

// round 12
// speedup vs baseline: 1.8117x; 1.7041x over previous
#include <cuda_runtime.h>
#include <cuda_fp16.h>
#include <math.h>
#include <stdint.h>

#define B_ 16
#define S_ 2048
#define D_ 256
#define NT 256
#define LOG2E 1.4426950408889634f

// ================= compacted fp16 hi/lo scratch =================
__device__ __half g_Khi[(size_t)B_*D_*S_];   // [b][d][jc]  compacted cols
__device__ __half g_Klo[(size_t)B_*D_*S_];
__device__ __half g_Vhi[(size_t)B_*S_*D_];   // [b][jc][dv] compacted rows
__device__ int    g_nb[B_];
__device__ int    g_idx[(size_t)B_*S_];

__device__ __forceinline__ uint32_t smem_u32(const void* p) {
    uint32_t a;
    asm("{ .reg .u64 t; cvta.to.shared.u64 t, %1; cvt.u32.u64 %0, t; }" : "=r"(a) : "l"(p));
    return a;
}

// fast exp2 on fma/alu pipes (no MUFU)
__device__ __forceinline__ float exp2p(float y) {
    y = fmaxf(y, -125.f);
    float z = __fadd_rn(y, 12582912.f);
    int   n = __float_as_int(z) - 0x4B400000;
    float f = __fsub_rn(y, __fadd_rn(z, -12582912.f));
    float p = 1.33335581e-3f;
    p = fmaf(p, f, 9.61812910e-3f);
    p = fmaf(p, f, 5.55041087e-2f);
    p = fmaf(p, f, 2.40226512e-1f);
    p = fmaf(p, f, 6.93147182e-1f);
    p = fmaf(p, f, 1.0f);
    return __int_as_float(__float_as_int(p) + (n << 23));
}

#define LDSM4(r, a) \
    asm volatile("ldmatrix.sync.aligned.m8n8.x4.shared.b16 {%0,%1,%2,%3}, [%4];" \
        : "=r"((r)[0]), "=r"((r)[1]), "=r"((r)[2]), "=r"((r)[3]) : "r"(a))

#define LDSM4T(r, a) \
    asm volatile("ldmatrix.sync.aligned.m8n8.x4.trans.shared.b16 {%0,%1,%2,%3}, [%4];" \
        : "=r"((r)[0]), "=r"((r)[1]), "=r"((r)[2]), "=r"((r)[3]) : "r"(a))

#define MMA(d, a, b0, b1) \
    asm volatile("mma.sync.aligned.m16n8k16.row.col.f32.f16.f16.f32 " \
        "{%0,%1,%2,%3},{%4,%5,%6,%7},{%8,%9},{%0,%1,%2,%3};" \
        : "+f"((d)[0]), "+f"((d)[1]), "+f"((d)[2]), "+f"((d)[3]) \
        : "r"((a)[0]), "r"((a)[1]), "r"((a)[2]), "r"((a)[3]), "r"(b0), "r"(b1))

#define PACKH2(d, lo, hi) \
    asm("cvt.rn.f16x2.f32 %0, %1, %2;" : "=r"(d) : "f"(hi), "f"(lo))

#define CPASYNC16(dst, src) \
    asm volatile("cp.async.cg.shared.global [%0], [%1], 16;" :: "r"(dst), "l"(src))
#define CPCOMMIT()   asm volatile("cp.async.commit_group;" ::: "memory")
#define CPWAIT_ALL() asm volatile("cp.async.wait_group 0;" ::: "memory")

// ================= prep kernels =================
// 1) per-batch compaction index (block scan)
__global__ void build_idx(const int* __restrict__ mask) {
    __shared__ int s0[256], s1[256];
    const int b = blockIdx.x, t = threadIdx.x;
    const int* mb = mask + (size_t)b * S_;
    int my[8], c = 0;
    #pragma unroll
    for (int i = 0; i < 8; i++) { my[i] = mb[t * 8 + i]; c += (my[i] != 0); }
    s0[t] = c;
    __syncthreads();
    int* in = s0; int* out = s1;
    for (int d = 1; d < 256; d <<= 1) {
        out[t] = in[t] + ((t >= d) ? in[t - d] : 0);
        __syncthreads();
        int* tmp = in; in = out; out = tmp;
    }
    int pos = in[t] - c;              // exclusive prefix
    #pragma unroll
    for (int i = 0; i < 8; i++)
        if (my[i]) g_idx[(size_t)b * S_ + (pos++)] = t * 8 + i;
    if (t == 255) g_nb[b] = in[255];
}

// 2) gather + split K: out [b][d][jc], zero pad to 32-multiple
__global__ void gather_split_k(const float* __restrict__ k) {
    size_t i = (size_t)blockIdx.x * blockDim.x + threadIdx.x;  // over B*D*(S/4)
    int jc4 = (int)(i % (S_ / 4)) * 4;
    size_t bd = i / (S_ / 4);
    int b = (int)(bd / D_);
    int nb = g_nb[b];
    int npad = (nb + 31) & ~31;
    if (jc4 >= npad) return;
    const int* idx = g_idx + (size_t)b * S_;
    const float* krow = k + bd * S_;
    __half h[4], l[4];
    #pragma unroll
    for (int t = 0; t < 4; t++) {
        int jc = jc4 + t;
        float x = (jc < nb) ? krow[idx[jc]] : 0.f;
        h[t] = __float2half_rn(x);
        l[t] = __float2half_rn(x - __half2float(h[t]));
    }
    size_t o = bd * S_ + jc4;
    *(uint2*)(g_Khi + o) = *(uint2*)h;
    *(uint2*)(g_Klo + o) = *(uint2*)l;
}

// 3) gather V rows: out [b][jc][dv], zero pad
__global__ void gather_v(const float* __restrict__ v) {
    int jc = blockIdx.x, b = blockIdx.y, t = threadIdx.x;
    int nb = g_nb[b];
    int npad = (nb + 31) & ~31;
    if (jc >= npad) return;
    __half h[4] = {__half(0.f), __half(0.f), __half(0.f), __half(0.f)};
    if (jc < nb) {
        int j = g_idx[(size_t)b * S_ + jc];
        float4 f = *(const float4*)(v + ((size_t)b * S_ + j) * D_ + t * 4);
        h[0] = __float2half_rn(f.x); h[1] = __float2half_rn(f.y);
        h[2] = __float2half_rn(f.z); h[3] = __float2half_rn(f.w);
    }
    *(uint2*)(g_Vhi + ((size_t)b * S_ + jc) * D_ + t * 4) = *(uint2*)h;
}

// ================= main kernel =================
#define QSP    65536
#define OFF_K  131072
#define KBUF   32768
#define KSP    16384
#define OFF_V  196608
#define VBUF   16384
#define SMEM_SZ 229376

__global__ void __launch_bounds__(NT, 1)
attn_hmma(const float* __restrict__ qf, float* __restrict__ out)
{
    extern __shared__ char smem[];
    const uint32_t sb = smem_u32(smem);
    const int tid  = threadIdx.x;
    const int lane = tid & 31;
    const int warp = tid >> 5;
    const int b    = blockIdx.y;
    const int q0   = blockIdx.x * 128;

    const __half* khb = g_Khi + (size_t)b * D_ * S_;
    const __half* klb = g_Klo + (size_t)b * D_ * S_;
    const __half* vhb = g_Vhi + (size_t)b * S_ * D_;
    const float*  qsrc = qf + ((size_t)b * S_ + q0) * D_;
    const int nbv = g_nb[b];
    const int ntiles = (nbv + 31) >> 5;

    // ---- prologue: Q fp32 -> hi/lo via K region as staging ----
    #pragma unroll
    for (int p = 0; p < 2; p++) {
        #pragma unroll
        for (int it = 0; it < 16; it++) {
            int idx = tid + it * NT;
            int r = idx >> 6, c = idx & 63;
            CPASYNC16(sb + OFF_K + r * 1024 + c * 16,
                      qsrc + (size_t)(64 * p + r) * D_ + c * 4);
        }
        CPCOMMIT();
        CPWAIT_ALL();
        __syncthreads();
        #pragma unroll
        for (int it = 0; it < 8; it++) {
            int idx = tid + it * NT;
            int rl = idx >> 5, u = idx & 31;
            int r = 64 * p + rl;
            float4 f0 = *(const float4*)(smem + OFF_K + rl * 1024 + u * 32);
            float4 f1 = *(const float4*)(smem + OFF_K + rl * 1024 + u * 32 + 16);
            __half2 h01 = __floats2half2_rn(f0.x, f0.y);
            __half2 h23 = __floats2half2_rn(f0.z, f0.w);
            __half2 h45 = __floats2half2_rn(f1.x, f1.y);
            __half2 h67 = __floats2half2_rn(f1.z, f1.w);
            float2 g01 = __half22float2(h01), g23 = __half22float2(h23);
            float2 g45 = __half22float2(h45), g67 = __half22float2(h67);
            __half2 l01 = __floats2half2_rn(f0.x - g01.x, f0.y - g01.y);
            __half2 l23 = __floats2half2_rn(f0.z - g23.x, f0.w - g23.y);
            __half2 l45 = __floats2half2_rn(f1.x - g45.x, f1.y - g45.y);
            __half2 l67 = __floats2half2_rn(f1.z - g67.x, f1.w - g67.y);
            uint32_t off = r * 512 + ((u ^ (r & 7)) << 4);
            *(uint4*)(smem + off)       = make_uint4(*(uint32_t*)&h01, *(uint32_t*)&h23,
                                                     *(uint32_t*)&h45, *(uint32_t*)&h67);
            *(uint4*)(smem + off + QSP) = make_uint4(*(uint32_t*)&l01, *(uint32_t*)&l23,
                                                     *(uint32_t*)&l45, *(uint32_t*)&l67);
        }
        __syncthreads();
    }

    // ---- zero V buf 1 (read by harmless jt=0 GEMM2 with Ph=0) ----
    #pragma unroll
    for (int it = 0; it < 4; it++) {
        int idx = tid + it * NT;
        *(uint4*)(smem + OFF_V + VBUF + idx * 16) = make_uint4(0, 0, 0, 0);
    }

    // ---- issue K(0) into buf 0 ----
    #pragma unroll
    for (int it = 0; it < 4; it++) {
        int idx = tid + it * NT;
        int r = idx >> 2, u = idx & 3;
        uint32_t dst = sb + OFF_K + r * 64 + ((u ^ ((r >> 1) & 3)) << 4);
        CPASYNC16(dst,       khb + (size_t)r * S_ + u * 8);
        CPASYNC16(dst + KSP, klb + (size_t)r * S_ + u * 8);
    }
    CPCOMMIT();

    // ---- lane geometry ----
    const int mrow = lane & 7;
    const int rowA = warp * 16 + mrow + (((lane >> 3) & 1) << 3);
    const int hiA  = lane >> 4;
    const int krb  = ((lane >> 3) & 1) * 8 + (lane & 7);
    const int ul   = lane >> 4;

    uint32_t aQ[4];
    #pragma unroll
    for (int m = 0; m < 4; m++)
        aQ[m] = sb + rowA * 512 + ((((2 * m + hiA)) ^ mrow) << 4);

    uint32_t kbs[2], vrel[4];
    #pragma unroll
    for (int nh = 0; nh < 2; nh++)
        kbs[nh] = (uint32_t)(krb * 64 + (((nh * 2 + ul) ^ ((krb >> 1) & 3)) << 4));
    #pragma unroll
    for (int i = 0; i < 4; i++)
        vrel[i] = (uint32_t)(krb * 512 + (((i * 2 + ul) ^ (krb & 7)) << 4));

    float O[32][4];
    #pragma unroll
    for (int i = 0; i < 32; i++) { O[i][0] = O[i][1] = O[i][2] = O[i][3] = 0.f; }
    float mr0 = -INFINITY, mr1 = -INFINITY, lr0 = 0.f, lr1 = 0.f;
    uint32_t PhP[4][2];
    #pragma unroll
    for (int i = 0; i < 4; i++) { PhP[i][0] = 0u; PhP[i][1] = 0u; }

    const int c2 = (lane & 3) * 2;
    const int g  = lane >> 2;

    for (int jt = 0; jt < ntiles; jt++) {
        const int kt = jt * 32;
        const int p  = jt & 1;
        const uint32_t kB = sb + OFF_K + (uint32_t)p * KBUF;
        const uint32_t vB = sb + OFF_V + (uint32_t)(p ^ 1) * VBUF;   // V(jt-1)

        CPWAIT_ALL();          // K(jt) + V(jt-1) complete
        __syncthreads();

        // ---- issue V(jt) -> vbuf p ----
        #pragma unroll
        for (int it = 0; it < 4; it++) {
            int idx = tid + it * NT;
            int r = idx >> 5, u = idx & 31;
            uint32_t dst = sb + OFF_V + (uint32_t)p * VBUF + r * 512
                         + ((u >> 3) << 7) + (((u & 7) ^ (r & 7)) << 4);
            CPASYNC16(dst, vhb + (size_t)(kt + r) * D_ + u * 8);
        }
        CPCOMMIT();
        // ---- issue K(jt+1) -> kbuf p^1 (clamped; last-tile reload unread) ----
        {
            const int ktn = ((jt + 1 < ntiles) ? jt + 1 : jt) * 32;
            const uint32_t kbN = sb + OFF_K + (uint32_t)(p ^ 1) * KBUF;
            #pragma unroll
            for (int it = 0; it < 4; it++) {
                int idx = tid + it * NT;
                int r = idx >> 2, u = idx & 3;
                uint32_t dst = kbN + r * 64 + ((u ^ ((r >> 1) & 3)) << 4);
                CPASYNC16(dst,       khb + (size_t)r * S_ + ktn + u * 8);
                CPASYNC16(dst + KSP, klb + (size_t)r * S_ + ktn + u * 8);
            }
            CPCOMMIT();
        }

        // ---- fused: GEMM1(jt) + GEMM2(jt-1), interleaved in 4 chunks ----
        float s[4][4];
        #pragma unroll
        for (int i = 0; i < 4; i++) s[i][0] = s[i][1] = s[i][2] = s[i][3] = 0.f;

        const uint32_t kb0 = kB + kbs[0];
        const uint32_t kb1 = kB + kbs[1];
        #pragma unroll
        for (int c = 0; c < 4; c++) {
            {
                const int kkv = c >> 1;
                uint32_t ap[4] = { PhP[2*kkv][0], PhP[2*kkv][1],
                                   PhP[2*kkv+1][0], PhP[2*kkv+1][1] };
                #pragma unroll
                for (int n2 = 0; n2 < 8; n2++) {
                    int nn = (c & 1) * 8 + n2;
                    uint32_t bh[4];
                    LDSM4T(bh, vB + vrel[nn & 3] + ((nn >> 2) << 7) + kkv * 8192);
                    MMA(O[2*nn],   ap, bh[0], bh[1]);
                    MMA(O[2*nn+1], ap, bh[2], bh[3]);
                }
            }
            #pragma unroll
            for (int k2 = 0; k2 < 4; k2++) {
                const int kk = c * 4 + k2;
                uint32_t ah[4], al[4], bh[4], bl[4], bh2[4], bl2[4];
                LDSM4(ah, aQ[k2] + c * 128);
                LDSM4(al, aQ[k2] + c * 128 + QSP);
                LDSM4T(bh,  kb0 + kk * 1024);
                LDSM4T(bl,  kb0 + kk * 1024 + KSP);
                LDSM4T(bh2, kb1 + kk * 1024);
                LDSM4T(bl2, kb1 + kk * 1024 + KSP);
                MMA(s[0], ah, bh[0], bh[1]);
                MMA(s[0], al, bh[0], bh[1]);
                MMA(s[0], ah, bl[0], bl[1]);
                MMA(s[1], ah, bh[2], bh[3]);
                MMA(s[1], al, bh[2], bh[3]);
                MMA(s[1], ah, bl[2], bl[3]);
                MMA(s[2], ah, bh2[0], bh2[1]);
                MMA(s[2], al, bh2[0], bh2[1]);
                MMA(s[2], ah, bl2[0], bl2[1]);
                MMA(s[3], ah, bh2[2], bh2[3]);
                MMA(s[3], al, bh2[2], bh2[3]);
                MMA(s[3], ah, bl2[2], bl2[3]);
            }
        }

        // ---- tail-tile guard + online softmax ----
        {
            if (jt == ntiles - 1) {
                #pragma unroll
                for (int nf = 0; nf < 4; nf++) {
                    int col = kt + nf * 8 + c2;
                    if (col     >= nbv) { s[nf][0] = -1.0e9f; s[nf][2] = -1.0e9f; }
                    if (col + 1 >= nbv) { s[nf][1] = -1.0e9f; s[nf][3] = -1.0e9f; }
                }
            }
            float m0 = -INFINITY, m1 = -INFINITY;
            #pragma unroll
            for (int nf = 0; nf < 4; nf++) {
                m0 = fmaxf(m0, fmaxf(s[nf][0], s[nf][1]));
                m1 = fmaxf(m1, fmaxf(s[nf][2], s[nf][3]));
            }
            m0 = fmaxf(m0, __shfl_xor_sync(0xffffffffu, m0, 1));
            m0 = fmaxf(m0, __shfl_xor_sync(0xffffffffu, m0, 2));
            m1 = fmaxf(m1, __shfl_xor_sync(0xffffffffu, m1, 1));
            m1 = fmaxf(m1, __shfl_xor_sync(0xffffffffu, m1, 2));

            float mn0 = fmaxf(mr0, m0), mn1 = fmaxf(mr1, m1);
            float sc0 = exp2p((mr0 - mn0) * LOG2E);
            float sc1 = exp2p((mr1 - mn1) * LOG2E);
            mr0 = mn0; mr1 = mn1;
            float nb0 = -mn0 * LOG2E, nb1 = -mn1 * LOG2E;
            float rs0 = 0.f, rs1 = 0.f;

            #pragma unroll
            for (int nf = 0; nf < 4; nf++) {
                float p0 = exp2p(fmaf(s[nf][0], LOG2E, nb0));
                float p1 = exp2p(fmaf(s[nf][1], LOG2E, nb0));
                float p2 = exp2p(fmaf(s[nf][2], LOG2E, nb1));
                float p3 = exp2p(fmaf(s[nf][3], LOG2E, nb1));
                rs0 += p0 + p1;
                rs1 += p2 + p3;
                PACKH2(PhP[nf][0], p0, p1);
                PACKH2(PhP[nf][1], p2, p3);
            }
            lr0 = lr0 * sc0 + rs0;
            lr1 = lr1 * sc1 + rs1;

            if (__any_sync(0xffffffffu, (sc0 != 1.0f) || (sc1 != 1.0f))) {
                #pragma unroll
                for (int i = 0; i < 32; i++) {
                    O[i][0] *= sc0; O[i][1] *= sc0;
                    O[i][2] *= sc1; O[i][3] *= sc1;
                }
            }
        }
    }

    // ---- peeled GEMM2(last): V(last) in vbuf (ntiles-1)&1 ----
    CPWAIT_ALL();
    __syncthreads();
    {
        const uint32_t vB = sb + OFF_V + (uint32_t)((ntiles - 1) & 1) * VBUF;
        #pragma unroll
        for (int kk = 0; kk < 2; kk++) {
            uint32_t ap[4] = { PhP[2*kk][0], PhP[2*kk][1], PhP[2*kk+1][0], PhP[2*kk+1][1] };
            #pragma unroll
            for (int nn = 0; nn < 16; nn++) {
                uint32_t bh[4];
                LDSM4T(bh, vB + vrel[nn & 3] + ((nn >> 2) << 7) + kk * 8192);
                MMA(O[2*nn],   ap, bh[0], bh[1]);
                MMA(O[2*nn+1], ap, bh[2], bh[3]);
            }
        }
    }

    // ---- epilogue ----
    lr0 += __shfl_xor_sync(0xffffffffu, lr0, 1);
    lr0 += __shfl_xor_sync(0xffffffffu, lr0, 2);
    lr1 += __shfl_xor_sync(0xffffffffu, lr1, 1);
    lr1 += __shfl_xor_sync(0xffffffffu, lr1, 2);
    float inv0 = 1.f / (lr0 * 16.0f);
    float inv1 = 1.f / (lr1 * 16.0f);

    float* ob = out + (size_t)b * D_ * S_;
    const int qg = q0 + warp * 16 + g;
    #pragma unroll
    for (int nn = 0; nn < 32; nn++) {
        int dv = nn * 8 + c2;
        ob[(size_t)dv * S_ + qg]           = O[nn][0] * inv0;
        ob[(size_t)(dv + 1) * S_ + qg]     = O[nn][1] * inv0;
        ob[(size_t)dv * S_ + qg + 8]       = O[nn][2] * inv1;
        ob[(size_t)(dv + 1) * S_ + qg + 8] = O[nn][3] * inv1;
    }
}

// ================= launcher =================
extern "C" void kernel_launch(void* const* d_in, const int* in_sizes, int n_in,
                              void* d_out, int out_size)
{
    (void)in_sizes; (void)n_in; (void)out_size;
    const float* q    = (const float*)d_in[0];
    const float* k    = (const float*)d_in[1];
    const float* v    = (const float*)d_in[2];
    const int*   mask = (const int*)d_in[3];
    float* out = (float*)d_out;

    build_idx<<<B_, 256>>>(mask);
    {
        size_t total = (size_t)B_ * D_ * (S_ / 4);
        gather_split_k<<<(unsigned)((total + 255) / 256), 256>>>(k);
    }
    gather_v<<<dim3(S_, B_), 64>>>(v);

    cudaFuncSetAttribute(attn_hmma, cudaFuncAttributeMaxDynamicSharedMemorySize, SMEM_SZ);
    attn_hmma<<<dim3(S_ / 128, B_), NT, SMEM_SZ>>>(q, out);
}

// round 13
// speedup vs baseline: 1.9813x; 1.0936x over previous
#include <cuda_runtime.h>
#include <cuda_fp16.h>
#include <math.h>
#include <stdint.h>

#define B_ 16
#define S_ 2048
#define D_ 256
#define NT 256
#define LOG2E 1.4426950408889634f

// ================= compacted fp16 hi/lo scratch =================
__device__ __half g_Khi[(size_t)B_*D_*S_];   // [b][d][jc]  compacted cols
__device__ __half g_Klo[(size_t)B_*D_*S_];
__device__ __half g_Vhi[(size_t)B_*S_*D_];   // [b][jc][dv] compacted rows
__device__ int    g_nb[B_];
__device__ int    g_idx[(size_t)B_*S_];

__device__ __forceinline__ uint32_t smem_u32(const void* p) {
    uint32_t a;
    asm("{ .reg .u64 t; cvta.to.shared.u64 t, %1; cvt.u32.u64 %0, t; }" : "=r"(a) : "l"(p));
    return a;
}

// fast exp2 on fma/alu pipes (no MUFU)
__device__ __forceinline__ float exp2p(float y) {
    y = fmaxf(y, -125.f);
    float z = __fadd_rn(y, 12582912.f);
    int   n = __float_as_int(z) - 0x4B400000;
    float f = __fsub_rn(y, __fadd_rn(z, -12582912.f));
    float p = 1.33335581e-3f;
    p = fmaf(p, f, 9.61812910e-3f);
    p = fmaf(p, f, 5.55041087e-2f);
    p = fmaf(p, f, 2.40226512e-1f);
    p = fmaf(p, f, 6.93147182e-1f);
    p = fmaf(p, f, 1.0f);
    return __int_as_float(__float_as_int(p) + (n << 23));
}

#define LDSM4(r, a) \
    asm volatile("ldmatrix.sync.aligned.m8n8.x4.shared.b16 {%0,%1,%2,%3}, [%4];" \
        : "=r"((r)[0]), "=r"((r)[1]), "=r"((r)[2]), "=r"((r)[3]) : "r"(a))

#define LDSM4T(r, a) \
    asm volatile("ldmatrix.sync.aligned.m8n8.x4.trans.shared.b16 {%0,%1,%2,%3}, [%4];" \
        : "=r"((r)[0]), "=r"((r)[1]), "=r"((r)[2]), "=r"((r)[3]) : "r"(a))

#define MMA(d, a, b0, b1) \
    asm volatile("mma.sync.aligned.m16n8k16.row.col.f32.f16.f16.f32 " \
        "{%0,%1,%2,%3},{%4,%5,%6,%7},{%8,%9},{%0,%1,%2,%3};" \
        : "+f"((d)[0]), "+f"((d)[1]), "+f"((d)[2]), "+f"((d)[3]) \
        : "r"((a)[0]), "r"((a)[1]), "r"((a)[2]), "r"((a)[3]), "r"(b0), "r"(b1))

#define PACKH2(d, lo, hi) \
    asm("cvt.rn.f16x2.f32 %0, %1, %2;" : "=r"(d) : "f"(hi), "f"(lo))

#define CPASYNC16(dst, src) \
    asm volatile("cp.async.cg.shared.global [%0], [%1], 16;" :: "r"(dst), "l"(src))
#define CPCOMMIT()   asm volatile("cp.async.commit_group;" ::: "memory")
#define CPWAIT_ALL() asm volatile("cp.async.wait_group 0;" ::: "memory")

// ================= prep kernels =================
__global__ void build_idx(const int* __restrict__ mask) {
    __shared__ int s0[256], s1[256];
    const int b = blockIdx.x, t = threadIdx.x;
    const int* mb = mask + (size_t)b * S_;
    int my[8], c = 0;
    #pragma unroll
    for (int i = 0; i < 8; i++) { my[i] = mb[t * 8 + i]; c += (my[i] != 0); }
    s0[t] = c;
    __syncthreads();
    int* in = s0; int* out = s1;
    for (int d = 1; d < 256; d <<= 1) {
        out[t] = in[t] + ((t >= d) ? in[t - d] : 0);
        __syncthreads();
        int* tmp = in; in = out; out = tmp;
    }
    int pos = in[t] - c;
    #pragma unroll
    for (int i = 0; i < 8; i++)
        if (my[i]) g_idx[(size_t)b * S_ + (pos++)] = t * 8 + i;
    if (t == 255) g_nb[b] = in[255];
}

// gather + split K: out [b][d][jc], zero pad to 64-multiple
__global__ void gather_split_k(const float* __restrict__ k) {
    size_t i = (size_t)blockIdx.x * blockDim.x + threadIdx.x;  // over B*D*(S/4)
    int jc4 = (int)(i % (S_ / 4)) * 4;
    size_t bd = i / (S_ / 4);
    int b = (int)(bd / D_);
    int nb = g_nb[b];
    int npad = (nb + 63) & ~63;
    if (jc4 >= npad) return;
    const int* idx = g_idx + (size_t)b * S_;
    const float* krow = k + bd * S_;
    __half h[4], l[4];
    #pragma unroll
    for (int t = 0; t < 4; t++) {
        int jc = jc4 + t;
        float x = (jc < nb) ? krow[idx[jc]] : 0.f;
        h[t] = __float2half_rn(x);
        l[t] = __float2half_rn(x - __half2float(h[t]));
    }
    size_t o = bd * S_ + jc4;
    *(uint2*)(g_Khi + o) = *(uint2*)h;
    *(uint2*)(g_Klo + o) = *(uint2*)l;
}

// gather V rows: out [b][jc][dv], zero pad; 256-thr blocks, 4 rows each
__global__ void gather_v(const float* __restrict__ v) {
    const int b = blockIdx.y, t = threadIdx.x;
    const int jc = blockIdx.x * 4 + (t >> 6);
    const int col = t & 63;
    int nb = g_nb[b];
    int npad = (nb + 63) & ~63;
    if (jc >= npad) return;
    __half h[4] = {__half(0.f), __half(0.f), __half(0.f), __half(0.f)};
    if (jc < nb) {
        int j = g_idx[(size_t)b * S_ + jc];
        float4 f = *(const float4*)(v + ((size_t)b * S_ + j) * D_ + col * 4);
        h[0] = __float2half_rn(f.x); h[1] = __float2half_rn(f.y);
        h[2] = __float2half_rn(f.z); h[3] = __float2half_rn(f.w);
    }
    *(uint2*)(g_Vhi + ((size_t)b * S_ + jc) * D_ + col * 4) = *(uint2*)h;
}

// ================= main kernel =================
// Q: [128 q][256 d] hi/lo, rows 512B                     (128 KB)
// K: [256 d][64 j]  hi/lo, rows 128B, single buf         ( 64 KB)
// V: [64 j][256 dv] hi, rows 512B, single buf            ( 32 KB)
#define QSP    65536
#define OFF_K  131072
#define KSP    32768
#define OFF_V  196608
#define SMEM_SZ 229376

__global__ void __launch_bounds__(NT, 1)
attn_hmma(const float* __restrict__ qf, float* __restrict__ out)
{
    extern __shared__ char smem[];
    const uint32_t sb = smem_u32(smem);
    const int tid  = threadIdx.x;
    const int lane = tid & 31;
    const int warp = tid >> 5;
    const int b    = blockIdx.y;
    const int q0   = blockIdx.x * 128;

    const __half* khb = g_Khi + (size_t)b * D_ * S_;
    const __half* klb = g_Klo + (size_t)b * D_ * S_;
    const __half* vhb = g_Vhi + (size_t)b * S_ * D_;
    const float*  qsrc = qf + ((size_t)b * S_ + q0) * D_;
    const int nbv = g_nb[b];
    const int ntiles = (nbv + 63) >> 6;

    // ---- prologue: Q fp32 -> hi/lo via K region as staging (2 x 64 rows) ----
    #pragma unroll
    for (int p = 0; p < 2; p++) {
        #pragma unroll
        for (int it = 0; it < 16; it++) {
            int idx = tid + it * NT;
            int r = idx >> 6, c = idx & 63;
            CPASYNC16(sb + OFF_K + r * 1024 + c * 16,
                      qsrc + (size_t)(64 * p + r) * D_ + c * 4);
        }
        CPCOMMIT();
        CPWAIT_ALL();
        __syncthreads();
        #pragma unroll
        for (int it = 0; it < 8; it++) {
            int idx = tid + it * NT;
            int rl = idx >> 5, u = idx & 31;
            int r = 64 * p + rl;
            float4 f0 = *(const float4*)(smem + OFF_K + rl * 1024 + u * 32);
            float4 f1 = *(const float4*)(smem + OFF_K + rl * 1024 + u * 32 + 16);
            __half2 h01 = __floats2half2_rn(f0.x, f0.y);
            __half2 h23 = __floats2half2_rn(f0.z, f0.w);
            __half2 h45 = __floats2half2_rn(f1.x, f1.y);
            __half2 h67 = __floats2half2_rn(f1.z, f1.w);
            float2 g01 = __half22float2(h01), g23 = __half22float2(h23);
            float2 g45 = __half22float2(h45), g67 = __half22float2(h67);
            __half2 l01 = __floats2half2_rn(f0.x - g01.x, f0.y - g01.y);
            __half2 l23 = __floats2half2_rn(f0.z - g23.x, f0.w - g23.y);
            __half2 l45 = __floats2half2_rn(f1.x - g45.x, f1.y - g45.y);
            __half2 l67 = __floats2half2_rn(f1.z - g67.x, f1.w - g67.y);
            uint32_t off = r * 512 + ((u ^ (r & 7)) << 4);
            *(uint4*)(smem + off)       = make_uint4(*(uint32_t*)&h01, *(uint32_t*)&h23,
                                                     *(uint32_t*)&h45, *(uint32_t*)&h67);
            *(uint4*)(smem + off + QSP) = make_uint4(*(uint32_t*)&l01, *(uint32_t*)&l23,
                                                     *(uint32_t*)&l45, *(uint32_t*)&l67);
        }
        __syncthreads();
    }

    // ---- issue K(0): 256 d-rows x 8 units, hi+lo ----
    #pragma unroll
    for (int it = 0; it < 8; it++) {
        int idx = tid + it * NT;
        int r = idx >> 3, u = idx & 7;
        uint32_t dst = sb + OFF_K + r * 128 + ((u ^ (r & 7)) << 4);
        CPASYNC16(dst,       khb + (size_t)r * S_ + u * 8);
        CPASYNC16(dst + KSP, klb + (size_t)r * S_ + u * 8);
    }
    CPCOMMIT();

    // ---- lane geometry ----
    const int mrow = lane & 7;
    const int rowA = warp * 16 + mrow + (((lane >> 3) & 1) << 3);
    const int hiA  = lane >> 4;
    const int krb  = ((lane >> 3) & 1) * 8 + (lane & 7);
    const int ul   = lane >> 4;

    uint32_t aQ[4];
    #pragma unroll
    for (int m = 0; m < 4; m++)
        aQ[m] = sb + rowA * 512 + ((((2 * m + hiA)) ^ mrow) << 4);

    uint32_t kbs[4], vrel[4];
    #pragma unroll
    for (int nn = 0; nn < 4; nn++)
        kbs[nn] = (uint32_t)(krb * 128 + (((2 * nn + ul) ^ (krb & 7)) << 4));
    #pragma unroll
    for (int i = 0; i < 4; i++)
        vrel[i] = (uint32_t)(krb * 512 + (((i * 2 + ul) ^ (krb & 7)) << 4));

    float O[32][4];
    #pragma unroll
    for (int i = 0; i < 32; i++) { O[i][0] = O[i][1] = O[i][2] = O[i][3] = 0.f; }
    float mr0 = -INFINITY, mr1 = -INFINITY, lr0 = 0.f, lr1 = 0.f;

    const int c2 = (lane & 3) * 2;
    const int g  = lane >> 2;

    for (int jt = 0; jt < ntiles; jt++) {
        const int kt = jt * 64;

        CPWAIT_ALL();          // K(jt) ready
        __syncthreads();       // all warps done GEMM2(jt-1) -> V buffer free

        // ---- issue V(jt): 64 j-rows x 32 units (overlaps GEMM1) ----
        #pragma unroll
        for (int it = 0; it < 8; it++) {
            int idx = tid + it * NT;
            int r = idx >> 5, u = idx & 31;
            uint32_t dst = sb + OFF_V + r * 512 + ((u >> 3) << 7)
                         + (((u & 7) ^ (r & 7)) << 4);
            CPASYNC16(dst, vhb + (size_t)(kt + r) * D_ + u * 8);
        }
        CPCOMMIT();

        // ---- GEMM1: S[16x64] = Qhi*Khi + Qlo*Khi + Qhi*Klo ----
        float s[8][4];
        #pragma unroll
        for (int i = 0; i < 8; i++) s[i][0] = s[i][1] = s[i][2] = s[i][3] = 0.f;

        #pragma unroll
        for (int kk = 0; kk < 16; kk++) {
            uint32_t ah[4], al[4];
            LDSM4(ah, aQ[kk & 3] + (kk >> 2) * 128);
            LDSM4(al, aQ[kk & 3] + (kk >> 2) * 128 + QSP);
            const uint32_t kbase = sb + OFF_K + kk * 2048;
            #pragma unroll
            for (int nn = 0; nn < 4; nn++) {
                uint32_t bh[4], bl[4];
                LDSM4T(bh, kbase + kbs[nn]);
                LDSM4T(bl, kbase + kbs[nn] + KSP);
                MMA(s[2*nn],   ah, bh[0], bh[1]);
                MMA(s[2*nn],   al, bh[0], bh[1]);
                MMA(s[2*nn],   ah, bl[0], bl[1]);
                MMA(s[2*nn+1], ah, bh[2], bh[3]);
                MMA(s[2*nn+1], al, bh[2], bh[3]);
                MMA(s[2*nn+1], ah, bl[2], bl[3]);
            }
        }

        // ---- tail guard + online softmax ----
        uint32_t Ph[8][2];
        {
            if (jt == ntiles - 1) {
                #pragma unroll
                for (int nf = 0; nf < 8; nf++) {
                    int col = kt + nf * 8 + c2;
                    if (col     >= nbv) { s[nf][0] = -1.0e9f; s[nf][2] = -1.0e9f; }
                    if (col + 1 >= nbv) { s[nf][1] = -1.0e9f; s[nf][3] = -1.0e9f; }
                }
            }
            float m0 = -INFINITY, m1 = -INFINITY;
            #pragma unroll
            for (int nf = 0; nf < 8; nf++) {
                m0 = fmaxf(m0, fmaxf(s[nf][0], s[nf][1]));
                m1 = fmaxf(m1, fmaxf(s[nf][2], s[nf][3]));
            }
            m0 = fmaxf(m0, __shfl_xor_sync(0xffffffffu, m0, 1));
            m0 = fmaxf(m0, __shfl_xor_sync(0xffffffffu, m0, 2));
            m1 = fmaxf(m1, __shfl_xor_sync(0xffffffffu, m1, 1));
            m1 = fmaxf(m1, __shfl_xor_sync(0xffffffffu, m1, 2));

            float mn0 = fmaxf(mr0, m0), mn1 = fmaxf(mr1, m1);
            float sc0 = exp2p((mr0 - mn0) * LOG2E);
            float sc1 = exp2p((mr1 - mn1) * LOG2E);
            mr0 = mn0; mr1 = mn1;
            float nb0 = -mn0 * LOG2E, nb1 = -mn1 * LOG2E;
            float rs0 = 0.f, rs1 = 0.f;

            #pragma unroll
            for (int nf = 0; nf < 8; nf++) {
                float p0 = exp2p(fmaf(s[nf][0], LOG2E, nb0));
                float p1 = exp2p(fmaf(s[nf][1], LOG2E, nb0));
                float p2 = exp2p(fmaf(s[nf][2], LOG2E, nb1));
                float p3 = exp2p(fmaf(s[nf][3], LOG2E, nb1));
                rs0 += p0 + p1;
                rs1 += p2 + p3;
                PACKH2(Ph[nf][0], p0, p1);
                PACKH2(Ph[nf][1], p2, p3);
            }
            lr0 = lr0 * sc0 + rs0;
            lr1 = lr1 * sc1 + rs1;

            if (__any_sync(0xffffffffu, (sc0 != 1.0f) || (sc1 != 1.0f))) {
                #pragma unroll
                for (int i = 0; i < 32; i++) {
                    O[i][0] *= sc0; O[i][1] *= sc0;
                    O[i][2] *= sc1; O[i][3] *= sc1;
                }
            }
        }

        CPWAIT_ALL();          // V(jt) ready
        __syncthreads();       // all warps done GEMM1 -> K buffer free

        // ---- issue K(jt+1) (overlaps GEMM2; clamped on last tile) ----
        {
            const int ktn = ((jt + 1 < ntiles) ? jt + 1 : jt) * 64;
            #pragma unroll
            for (int it = 0; it < 8; it++) {
                int idx = tid + it * NT;
                int r = idx >> 3, u = idx & 7;
                uint32_t dst = sb + OFF_K + r * 128 + ((u ^ (r & 7)) << 4);
                CPASYNC16(dst,       khb + (size_t)r * S_ + ktn + u * 8);
                CPASYNC16(dst + KSP, klb + (size_t)r * S_ + ktn + u * 8);
            }
            CPCOMMIT();
        }

        // ---- GEMM2: O += P * Vhi ----
        #pragma unroll
        for (int kk = 0; kk < 4; kk++) {
            uint32_t ap[4] = { Ph[2*kk][0], Ph[2*kk][1], Ph[2*kk+1][0], Ph[2*kk+1][1] };
            const uint32_t vbase = sb + OFF_V + kk * 8192;
            #pragma unroll
            for (int nn = 0; nn < 16; nn++) {
                uint32_t bh[4];
                LDSM4T(bh, vbase + vrel[nn & 3] + ((nn >> 2) << 7));
                MMA(O[2*nn],   ap, bh[0], bh[1]);
                MMA(O[2*nn+1], ap, bh[2], bh[3]);
            }
        }
    }
    CPWAIT_ALL();

    // ---- epilogue ----
    lr0 += __shfl_xor_sync(0xffffffffu, lr0, 1);
    lr0 += __shfl_xor_sync(0xffffffffu, lr0, 2);
    lr1 += __shfl_xor_sync(0xffffffffu, lr1, 1);
    lr1 += __shfl_xor_sync(0xffffffffu, lr1, 2);
    float inv0 = 1.f / (lr0 * 16.0f);
    float inv1 = 1.f / (lr1 * 16.0f);

    float* ob = out + (size_t)b * D_ * S_;
    const int qg = q0 + warp * 16 + g;
    #pragma unroll
    for (int nn = 0; nn < 32; nn++) {
        int dv = nn * 8 + c2;
        ob[(size_t)dv * S_ + qg]           = O[nn][0] * inv0;
        ob[(size_t)(dv + 1) * S_ + qg]     = O[nn][1] * inv0;
        ob[(size_t)dv * S_ + qg + 8]       = O[nn][2] * inv1;
        ob[(size_t)(dv + 1) * S_ + qg + 8] = O[nn][3] * inv1;
    }
}

// ================= launcher =================
extern "C" void kernel_launch(void* const* d_in, const int* in_sizes, int n_in,
                              void* d_out, int out_size)
{
    (void)in_sizes; (void)n_in; (void)out_size;
    const float* q    = (const float*)d_in[0];
    const float* k    = (const float*)d_in[1];
    const float* v    = (const float*)d_in[2];
    const int*   mask = (const int*)d_in[3];
    float* out = (float*)d_out;

    build_idx<<<B_, 256>>>(mask);
    {
        size_t total = (size_t)B_ * D_ * (S_ / 4);
        gather_split_k<<<(unsigned)((total + 255) / 256), 256>>>(k);
    }
    gather_v<<<dim3(S_ / 4, B_), 256>>>(v);

    cudaFuncSetAttribute(attn_hmma, cudaFuncAttributeMaxDynamicSharedMemorySize, SMEM_SZ);
    attn_hmma<<<dim3(S_ / 128, B_), NT, SMEM_SZ>>>(q, out);
}

// round 14
// speedup vs baseline: 2.4060x; 1.2143x over previous
#include <cuda_runtime.h>
#include <cuda_fp16.h>
#include <math.h>
#include <stdint.h>

#define B_ 16
#define S_ 2048
#define D_ 256
#define NT 256
#define LOG2E 1.4426950408889634f

// ================= compacted fp16 scratch =================
__device__ __half g_Khi[(size_t)B_*D_*S_];   // [b][d][jc]  compacted cols
__device__ __half g_Vhi[(size_t)B_*S_*D_];   // [b][jc][dv] compacted rows
__device__ int    g_nb[B_];
__device__ int    g_idx[(size_t)B_*S_];

__device__ __forceinline__ uint32_t smem_u32(const void* p) {
    uint32_t a;
    asm("{ .reg .u64 t; cvta.to.shared.u64 t, %1; cvt.u32.u64 %0, t; }" : "=r"(a) : "l"(p));
    return a;
}

// fast exp2 on fma/alu pipes (no MUFU)
__device__ __forceinline__ float exp2p(float y) {
    y = fmaxf(y, -125.f);
    float z = __fadd_rn(y, 12582912.f);
    int   n = __float_as_int(z) - 0x4B400000;
    float f = __fsub_rn(y, __fadd_rn(z, -12582912.f));
    float p = 1.33335581e-3f;
    p = fmaf(p, f, 9.61812910e-3f);
    p = fmaf(p, f, 5.55041087e-2f);
    p = fmaf(p, f, 2.40226512e-1f);
    p = fmaf(p, f, 6.93147182e-1f);
    p = fmaf(p, f, 1.0f);
    return __int_as_float(__float_as_int(p) + (n << 23));
}

#define LDSM4(r, a) \
    asm volatile("ldmatrix.sync.aligned.m8n8.x4.shared.b16 {%0,%1,%2,%3}, [%4];" \
        : "=r"((r)[0]), "=r"((r)[1]), "=r"((r)[2]), "=r"((r)[3]) : "r"(a))

#define LDSM4T(r, a) \
    asm volatile("ldmatrix.sync.aligned.m8n8.x4.trans.shared.b16 {%0,%1,%2,%3}, [%4];" \
        : "=r"((r)[0]), "=r"((r)[1]), "=r"((r)[2]), "=r"((r)[3]) : "r"(a))

#define MMA(d, a, b0, b1) \
    asm volatile("mma.sync.aligned.m16n8k16.row.col.f32.f16.f16.f32 " \
        "{%0,%1,%2,%3},{%4,%5,%6,%7},{%8,%9},{%0,%1,%2,%3};" \
        : "+f"((d)[0]), "+f"((d)[1]), "+f"((d)[2]), "+f"((d)[3]) \
        : "r"((a)[0]), "r"((a)[1]), "r"((a)[2]), "r"((a)[3]), "r"(b0), "r"(b1))

#define PACKH2(d, lo, hi) \
    asm("cvt.rn.f16x2.f32 %0, %1, %2;" : "=r"(d) : "f"(hi), "f"(lo))

#define CPASYNC16(dst, src) \
    asm volatile("cp.async.cg.shared.global [%0], [%1], 16;" :: "r"(dst), "l"(src))
#define CPCOMMIT()   asm volatile("cp.async.commit_group;" ::: "memory")
#define CPWAIT_ALL() asm volatile("cp.async.wait_group 0;" ::: "memory")

// ================= prep kernels =================
__global__ void build_idx(const int* __restrict__ mask) {
    __shared__ int s0[256], s1[256];
    const int b = blockIdx.x, t = threadIdx.x;
    const int* mb = mask + (size_t)b * S_;
    int my[8], c = 0;
    #pragma unroll
    for (int i = 0; i < 8; i++) { my[i] = mb[t * 8 + i]; c += (my[i] != 0); }
    s0[t] = c;
    __syncthreads();
    int* in = s0; int* out = s1;
    for (int d = 1; d < 256; d <<= 1) {
        out[t] = in[t] + ((t >= d) ? in[t - d] : 0);
        __syncthreads();
        int* tmp = in; in = out; out = tmp;
    }
    int pos = in[t] - c;
    #pragma unroll
    for (int i = 0; i < 8; i++)
        if (my[i]) g_idx[(size_t)b * S_ + (pos++)] = t * 8 + i;
    if (t == 255) g_nb[b] = in[255];
}

// gather K (hi only): out [b][d][jc], zero pad to 64-multiple
__global__ void gather_k(const float* __restrict__ k) {
    size_t i = (size_t)blockIdx.x * blockDim.x + threadIdx.x;  // over B*D*(S/4)
    int jc4 = (int)(i % (S_ / 4)) * 4;
    size_t bd = i / (S_ / 4);
    int b = (int)(bd / D_);
    int nb = g_nb[b];
    int npad = (nb + 63) & ~63;
    if (jc4 >= npad) return;
    const int* idx = g_idx + (size_t)b * S_;
    const float* krow = k + bd * S_;
    __half h[4];
    #pragma unroll
    for (int t = 0; t < 4; t++) {
        int jc = jc4 + t;
        float x = (jc < nb) ? krow[idx[jc]] : 0.f;
        h[t] = __float2half_rn(x);
    }
    *(uint2*)(g_Khi + bd * S_ + jc4) = *(uint2*)h;
}

// gather V rows: out [b][jc][dv], zero pad; 256-thr blocks, 4 rows each
__global__ void gather_v(const float* __restrict__ v) {
    const int b = blockIdx.y, t = threadIdx.x;
    const int jc = blockIdx.x * 4 + (t >> 6);
    const int col = t & 63;
    int nb = g_nb[b];
    int npad = (nb + 63) & ~63;
    if (jc >= npad) return;
    __half h[4] = {__half(0.f), __half(0.f), __half(0.f), __half(0.f)};
    if (jc < nb) {
        int j = g_idx[(size_t)b * S_ + jc];
        float4 f = *(const float4*)(v + ((size_t)b * S_ + j) * D_ + col * 4);
        h[0] = __float2half_rn(f.x); h[1] = __float2half_rn(f.y);
        h[2] = __float2half_rn(f.z); h[3] = __float2half_rn(f.w);
    }
    *(uint2*)(g_Vhi + ((size_t)b * S_ + jc) * D_ + col * 4) = *(uint2*)h;
}

// ================= main kernel =================
// Q: [128 q][256 d] hi/lo, rows 512B                     (128 KB)
// K: [256 d][64 j]  hi, rows 128B, single buf            ( 32 KB)
// V: [64 j][256 dv] hi, rows 512B, single buf            ( 32 KB)
#define QSP    65536
#define OFF_K  131072
#define OFF_V  163840
#define SMEM_SZ 196608

__global__ void __launch_bounds__(NT, 1)
attn_hmma(const float* __restrict__ qf, float* __restrict__ out)
{
    extern __shared__ char smem[];
    const uint32_t sb = smem_u32(smem);
    const int tid  = threadIdx.x;
    const int lane = tid & 31;
    const int warp = tid >> 5;
    const int b    = blockIdx.y;
    const int q0   = blockIdx.x * 128;

    const __half* khb = g_Khi + (size_t)b * D_ * S_;
    const __half* vhb = g_Vhi + (size_t)b * S_ * D_;
    const float*  qsrc = qf + ((size_t)b * S_ + q0) * D_;
    const int nbv = g_nb[b];
    const int ntiles = (nbv + 63) >> 6;

    // ---- prologue: Q fp32 -> hi/lo; staging spans K+V regions (64 KB) ----
    #pragma unroll
    for (int p = 0; p < 2; p++) {
        #pragma unroll
        for (int it = 0; it < 16; it++) {
            int idx = tid + it * NT;
            int r = idx >> 6, c = idx & 63;
            CPASYNC16(sb + OFF_K + r * 1024 + c * 16,
                      qsrc + (size_t)(64 * p + r) * D_ + c * 4);
        }
        CPCOMMIT();
        CPWAIT_ALL();
        __syncthreads();
        #pragma unroll
        for (int it = 0; it < 8; it++) {
            int idx = tid + it * NT;
            int rl = idx >> 5, u = idx & 31;
            int r = 64 * p + rl;
            float4 f0 = *(const float4*)(smem + OFF_K + rl * 1024 + u * 32);
            float4 f1 = *(const float4*)(smem + OFF_K + rl * 1024 + u * 32 + 16);
            __half2 h01 = __floats2half2_rn(f0.x, f0.y);
            __half2 h23 = __floats2half2_rn(f0.z, f0.w);
            __half2 h45 = __floats2half2_rn(f1.x, f1.y);
            __half2 h67 = __floats2half2_rn(f1.z, f1.w);
            float2 g01 = __half22float2(h01), g23 = __half22float2(h23);
            float2 g45 = __half22float2(h45), g67 = __half22float2(h67);
            __half2 l01 = __floats2half2_rn(f0.x - g01.x, f0.y - g01.y);
            __half2 l23 = __floats2half2_rn(f0.z - g23.x, f0.w - g23.y);
            __half2 l45 = __floats2half2_rn(f1.x - g45.x, f1.y - g45.y);
            __half2 l67 = __floats2half2_rn(f1.z - g67.x, f1.w - g67.y);
            uint32_t off = r * 512 + ((u ^ (r & 7)) << 4);
            *(uint4*)(smem + off)       = make_uint4(*(uint32_t*)&h01, *(uint32_t*)&h23,
                                                     *(uint32_t*)&h45, *(uint32_t*)&h67);
            *(uint4*)(smem + off + QSP) = make_uint4(*(uint32_t*)&l01, *(uint32_t*)&l23,
                                                     *(uint32_t*)&l45, *(uint32_t*)&l67);
        }
        __syncthreads();
    }

    // ---- issue K(0): 256 d-rows x 8 units ----
    #pragma unroll
    for (int it = 0; it < 8; it++) {
        int idx = tid + it * NT;
        int r = idx >> 3, u = idx & 7;
        uint32_t dst = sb + OFF_K + r * 128 + ((u ^ (r & 7)) << 4);
        CPASYNC16(dst, khb + (size_t)r * S_ + u * 8);
    }
    CPCOMMIT();

    // ---- lane geometry ----
    const int mrow = lane & 7;
    const int rowA = warp * 16 + mrow + (((lane >> 3) & 1) << 3);
    const int hiA  = lane >> 4;
    const int krb  = ((lane >> 3) & 1) * 8 + (lane & 7);
    const int ul   = lane >> 4;

    uint32_t aQ[4];
    #pragma unroll
    for (int m = 0; m < 4; m++)
        aQ[m] = sb + rowA * 512 + ((((2 * m + hiA)) ^ mrow) << 4);

    uint32_t kbs[4], vrel[4];
    #pragma unroll
    for (int nn = 0; nn < 4; nn++)
        kbs[nn] = (uint32_t)(krb * 128 + (((2 * nn + ul) ^ (krb & 7)) << 4));
    #pragma unroll
    for (int i = 0; i < 4; i++)
        vrel[i] = (uint32_t)(krb * 512 + (((i * 2 + ul) ^ (krb & 7)) << 4));

    float O[32][4];
    #pragma unroll
    for (int i = 0; i < 32; i++) { O[i][0] = O[i][1] = O[i][2] = O[i][3] = 0.f; }
    float mr0 = -INFINITY, mr1 = -INFINITY, lr0 = 0.f, lr1 = 0.f;

    const int c2 = (lane & 3) * 2;
    const int g  = lane >> 2;

    for (int jt = 0; jt < ntiles; jt++) {
        const int kt = jt * 64;

        CPWAIT_ALL();          // K(jt) ready
        __syncthreads();       // all warps done GEMM2(jt-1) -> V buffer free

        // ---- issue V(jt): 64 j-rows x 32 units (overlaps GEMM1) ----
        #pragma unroll
        for (int it = 0; it < 8; it++) {
            int idx = tid + it * NT;
            int r = idx >> 5, u = idx & 31;
            uint32_t dst = sb + OFF_V + r * 512 + ((u >> 3) << 7)
                         + (((u & 7) ^ (r & 7)) << 4);
            CPASYNC16(dst, vhb + (size_t)(kt + r) * D_ + u * 8);
        }
        CPCOMMIT();

        // ---- GEMM1: S[16x64] = Qhi*Khi + Qlo*Khi ----
        float s[8][4];
        #pragma unroll
        for (int i = 0; i < 8; i++) s[i][0] = s[i][1] = s[i][2] = s[i][3] = 0.f;

        #pragma unroll
        for (int kk = 0; kk < 16; kk++) {
            uint32_t ah[4], al[4];
            LDSM4(ah, aQ[kk & 3] + (kk >> 2) * 128);
            LDSM4(al, aQ[kk & 3] + (kk >> 2) * 128 + QSP);
            const uint32_t kbase = sb + OFF_K + kk * 2048;
            #pragma unroll
            for (int nn = 0; nn < 4; nn++) {
                uint32_t bh[4];
                LDSM4T(bh, kbase + kbs[nn]);
                MMA(s[2*nn],   ah, bh[0], bh[1]);
                MMA(s[2*nn],   al, bh[0], bh[1]);
                MMA(s[2*nn+1], ah, bh[2], bh[3]);
                MMA(s[2*nn+1], al, bh[2], bh[3]);
            }
        }

        // ---- tail guard + online softmax ----
        uint32_t Ph[8][2];
        {
            if (jt == ntiles - 1) {
                #pragma unroll
                for (int nf = 0; nf < 8; nf++) {
                    int col = kt + nf * 8 + c2;
                    if (col     >= nbv) { s[nf][0] = -1.0e9f; s[nf][2] = -1.0e9f; }
                    if (col + 1 >= nbv) { s[nf][1] = -1.0e9f; s[nf][3] = -1.0e9f; }
                }
            }
            float m0 = -INFINITY, m1 = -INFINITY;
            #pragma unroll
            for (int nf = 0; nf < 8; nf++) {
                m0 = fmaxf(m0, fmaxf(s[nf][0], s[nf][1]));
                m1 = fmaxf(m1, fmaxf(s[nf][2], s[nf][3]));
            }
            m0 = fmaxf(m0, __shfl_xor_sync(0xffffffffu, m0, 1));
            m0 = fmaxf(m0, __shfl_xor_sync(0xffffffffu, m0, 2));
            m1 = fmaxf(m1, __shfl_xor_sync(0xffffffffu, m1, 1));
            m1 = fmaxf(m1, __shfl_xor_sync(0xffffffffu, m1, 2));

            float mn0 = fmaxf(mr0, m0), mn1 = fmaxf(mr1, m1);
            float sc0 = exp2p((mr0 - mn0) * LOG2E);
            float sc1 = exp2p((mr1 - mn1) * LOG2E);
            mr0 = mn0; mr1 = mn1;
            float nb0 = -mn0 * LOG2E, nb1 = -mn1 * LOG2E;
            float rs0 = 0.f, rs1 = 0.f;

            #pragma unroll
            for (int nf = 0; nf < 8; nf++) {
                float p0 = exp2p(fmaf(s[nf][0], LOG2E, nb0));
                float p1 = exp2p(fmaf(s[nf][1], LOG2E, nb0));
                float p2 = exp2p(fmaf(s[nf][2], LOG2E, nb1));
                float p3 = exp2p(fmaf(s[nf][3], LOG2E, nb1));
                rs0 += p0 + p1;
                rs1 += p2 + p3;
                PACKH2(Ph[nf][0], p0, p1);
                PACKH2(Ph[nf][1], p2, p3);
            }
            lr0 = lr0 * sc0 + rs0;
            lr1 = lr1 * sc1 + rs1;

            if (__any_sync(0xffffffffu, (sc0 != 1.0f) || (sc1 != 1.0f))) {
                #pragma unroll
                for (int i = 0; i < 32; i++) {
                    O[i][0] *= sc0; O[i][1] *= sc0;
                    O[i][2] *= sc1; O[i][3] *= sc1;
                }
            }
        }

        CPWAIT_ALL();          // V(jt) ready
        __syncthreads();       // all warps done GEMM1 -> K buffer free

        // ---- issue K(jt+1) (overlaps GEMM2; clamped on last tile) ----
        {
            const int ktn = ((jt + 1 < ntiles) ? jt + 1 : jt) * 64;
            #pragma unroll
            for (int it = 0; it < 8; it++) {
                int idx = tid + it * NT;
                int r = idx >> 3, u = idx & 7;
                uint32_t dst = sb + OFF_K + r * 128 + ((u ^ (r & 7)) << 4);
                CPASYNC16(dst, khb + (size_t)r * S_ + ktn + u * 8);
            }
            CPCOMMIT();
        }

        // ---- GEMM2: O += P * Vhi ----
        #pragma unroll
        for (int kk = 0; kk < 4; kk++) {
            uint32_t ap[4] = { Ph[2*kk][0], Ph[2*kk][1], Ph[2*kk+1][0], Ph[2*kk+1][1] };
            const uint32_t vbase = sb + OFF_V + kk * 8192;
            #pragma unroll
            for (int nn = 0; nn < 16; nn++) {
                uint32_t bh[4];
                LDSM4T(bh, vbase + vrel[nn & 3] + ((nn >> 2) << 7));
                MMA(O[2*nn],   ap, bh[0], bh[1]);
                MMA(O[2*nn+1], ap, bh[2], bh[3]);
            }
        }
    }
    CPWAIT_ALL();

    // ---- epilogue ----
    lr0 += __shfl_xor_sync(0xffffffffu, lr0, 1);
    lr0 += __shfl_xor_sync(0xffffffffu, lr0, 2);
    lr1 += __shfl_xor_sync(0xffffffffu, lr1, 1);
    lr1 += __shfl_xor_sync(0xffffffffu, lr1, 2);
    float inv0 = 1.f / (lr0 * 16.0f);
    float inv1 = 1.f / (lr1 * 16.0f);

    float* ob = out + (size_t)b * D_ * S_;
    const int qg = q0 + warp * 16 + g;
    #pragma unroll
    for (int nn = 0; nn < 32; nn++) {
        int dv = nn * 8 + c2;
        ob[(size_t)dv * S_ + qg]           = O[nn][0] * inv0;
        ob[(size_t)(dv + 1) * S_ + qg]     = O[nn][1] * inv0;
        ob[(size_t)dv * S_ + qg + 8]       = O[nn][2] * inv1;
        ob[(size_t)(dv + 1) * S_ + qg + 8] = O[nn][3] * inv1;
    }
}

// ================= launcher =================
extern "C" void kernel_launch(void* const* d_in, const int* in_sizes, int n_in,
                              void* d_out, int out_size)
{
    (void)in_sizes; (void)n_in; (void)out_size;
    const float* q    = (const float*)d_in[0];
    const float* k    = (const float*)d_in[1];
    const float* v    = (const float*)d_in[2];
    const int*   mask = (const int*)d_in[3];
    float* out = (float*)d_out;

    build_idx<<<B_, 256>>>(mask);
    {
        size_t total = (size_t)B_ * D_ * (S_ / 4);
        gather_k<<<(unsigned)((total + 255) / 256), 256>>>(k);
    }
    gather_v<<<dim3(S_ / 4, B_), 256>>>(v);

    cudaFuncSetAttribute(attn_hmma, cudaFuncAttributeMaxDynamicSharedMemorySize, SMEM_SZ);
    attn_hmma<<<dim3(S_ / 128, B_), NT, SMEM_SZ>>>(q, out);
}

// round 15
// speedup vs baseline: 2.4558x; 1.0207x over previous
#include <cuda_runtime.h>
#include <cuda_fp16.h>
#include <math.h>
#include <stdint.h>

#define B_ 16
#define S_ 2048
#define D_ 256
#define NT 256
#define LOG2E 1.4426950408889634f

// ================= compacted fp16 scratch =================
__device__ __half g_Khi[(size_t)B_*D_*S_];   // [b][d][jc]  compacted cols
__device__ __half g_Vhi[(size_t)B_*S_*D_];   // [b][jc][dv] compacted rows
__device__ int    g_nb[B_];
__device__ int    g_idx[(size_t)B_*S_];

__device__ __forceinline__ uint32_t smem_u32(const void* p) {
    uint32_t a;
    asm("{ .reg .u64 t; cvta.to.shared.u64 t, %1; cvt.u32.u64 %0, t; }" : "=r"(a) : "l"(p));
    return a;
}

// fast exp2 on fma/alu pipes (no MUFU)
__device__ __forceinline__ float exp2p(float y) {
    y = fmaxf(y, -125.f);
    float z = __fadd_rn(y, 12582912.f);
    int   n = __float_as_int(z) - 0x4B400000;
    float f = __fsub_rn(y, __fadd_rn(z, -12582912.f));
    float p = 1.33335581e-3f;
    p = fmaf(p, f, 9.61812910e-3f);
    p = fmaf(p, f, 5.55041087e-2f);
    p = fmaf(p, f, 2.40226512e-1f);
    p = fmaf(p, f, 6.93147182e-1f);
    p = fmaf(p, f, 1.0f);
    return __int_as_float(__float_as_int(p) + (n << 23));
}

#define LDSM4(r, a) \
    asm volatile("ldmatrix.sync.aligned.m8n8.x4.shared.b16 {%0,%1,%2,%3}, [%4];" \
        : "=r"((r)[0]), "=r"((r)[1]), "=r"((r)[2]), "=r"((r)[3]) : "r"(a))

#define LDSM4T(r, a) \
    asm volatile("ldmatrix.sync.aligned.m8n8.x4.trans.shared.b16 {%0,%1,%2,%3}, [%4];" \
        : "=r"((r)[0]), "=r"((r)[1]), "=r"((r)[2]), "=r"((r)[3]) : "r"(a))

#define MMA(d, a, b0, b1) \
    asm volatile("mma.sync.aligned.m16n8k16.row.col.f32.f16.f16.f32 " \
        "{%0,%1,%2,%3},{%4,%5,%6,%7},{%8,%9},{%0,%1,%2,%3};" \
        : "+f"((d)[0]), "+f"((d)[1]), "+f"((d)[2]), "+f"((d)[3]) \
        : "r"((a)[0]), "r"((a)[1]), "r"((a)[2]), "r"((a)[3]), "r"(b0), "r"(b1))

#define PACKH2(d, lo, hi) \
    asm("cvt.rn.f16x2.f32 %0, %1, %2;" : "=r"(d) : "f"(hi), "f"(lo))

#define CPASYNC16(dst, src) \
    asm volatile("cp.async.cg.shared.global [%0], [%1], 16;" :: "r"(dst), "l"(src))
#define CPCOMMIT()   asm volatile("cp.async.commit_group;" ::: "memory")
#define CPWAIT_ALL() asm volatile("cp.async.wait_group 0;" ::: "memory")

// ================= prep kernels =================
__global__ void build_idx(const int* __restrict__ mask) {
    __shared__ int s0[256], s1[256];
    const int b = blockIdx.x, t = threadIdx.x;
    const int* mb = mask + (size_t)b * S_;
    int my[8], c = 0;
    #pragma unroll
    for (int i = 0; i < 8; i++) { my[i] = mb[t * 8 + i]; c += (my[i] != 0); }
    s0[t] = c;
    __syncthreads();
    int* in = s0; int* out = s1;
    for (int d = 1; d < 256; d <<= 1) {
        out[t] = in[t] + ((t >= d) ? in[t - d] : 0);
        __syncthreads();
        int* tmp = in; in = out; out = tmp;
    }
    int pos = in[t] - c;
    #pragma unroll
    for (int i = 0; i < 8; i++)
        if (my[i]) g_idx[(size_t)b * S_ + (pos++)] = t * 8 + i;
    if (t == 255) g_nb[b] = in[255];
}

// gather K (hi only): out [b][d][jc], zero pad to 64-multiple
__global__ void gather_k(const float* __restrict__ k) {
    size_t i = (size_t)blockIdx.x * blockDim.x + threadIdx.x;  // over B*D*(S/4)
    int jc4 = (int)(i % (S_ / 4)) * 4;
    size_t bd = i / (S_ / 4);
    int b = (int)(bd / D_);
    int nb = g_nb[b];
    int npad = (nb + 63) & ~63;
    if (jc4 >= npad) return;
    const int* idx = g_idx + (size_t)b * S_;
    const float* krow = k + bd * S_;
    __half h[4];
    #pragma unroll
    for (int t = 0; t < 4; t++) {
        int jc = jc4 + t;
        float x = (jc < nb) ? krow[idx[jc]] : 0.f;
        h[t] = __float2half_rn(x);
    }
    *(uint2*)(g_Khi + bd * S_ + jc4) = *(uint2*)h;
}

// gather V rows: out [b][jc][dv], zero pad; 256-thr blocks, 4 rows each
__global__ void gather_v(const float* __restrict__ v) {
    const int b = blockIdx.y, t = threadIdx.x;
    const int jc = blockIdx.x * 4 + (t >> 6);
    const int col = t & 63;
    int nb = g_nb[b];
    int npad = (nb + 63) & ~63;
    if (jc >= npad) return;
    __half h[4] = {__half(0.f), __half(0.f), __half(0.f), __half(0.f)};
    if (jc < nb) {
        int j = g_idx[(size_t)b * S_ + jc];
        float4 f = *(const float4*)(v + ((size_t)b * S_ + j) * D_ + col * 4);
        h[0] = __float2half_rn(f.x); h[1] = __float2half_rn(f.y);
        h[2] = __float2half_rn(f.z); h[3] = __float2half_rn(f.w);
    }
    *(uint2*)(g_Vhi + ((size_t)b * S_ + jc) * D_ + col * 4) = *(uint2*)h;
}

// ================= main kernel =================
// Q: [128 q][256 d] hi/lo, rows 512B                     (128 KB)
// K: [256 d][64 j]  hi, rows 128B, single buf            ( 32 KB)
// V: [64 j][256 dv] hi, rows 512B, single buf            ( 32 KB)
#define QSP    65536
#define OFF_K  131072
#define OFF_V  163840
#define SMEM_SZ 196608

__global__ void __launch_bounds__(NT, 1)
attn_hmma(const float* __restrict__ qf, float* __restrict__ out)
{
    extern __shared__ char smem[];
    const uint32_t sb = smem_u32(smem);
    const int tid  = threadIdx.x;
    const int lane = tid & 31;
    const int warp = tid >> 5;
    const int b    = blockIdx.y;
    const int q0   = blockIdx.x * 128;

    const __half* khb = g_Khi + (size_t)b * D_ * S_;
    const __half* vhb = g_Vhi + (size_t)b * S_ * D_;
    const float*  qsrc = qf + ((size_t)b * S_ + q0) * D_;
    const int nbv = g_nb[b];
    const int ntiles = (nbv + 63) >> 6;

    // ---- prologue: Q fp32 -> hi/lo; staging spans K+V regions (64 KB) ----
    #pragma unroll
    for (int p = 0; p < 2; p++) {
        #pragma unroll
        for (int it = 0; it < 16; it++) {
            int idx = tid + it * NT;
            int r = idx >> 6, c = idx & 63;
            CPASYNC16(sb + OFF_K + r * 1024 + c * 16,
                      qsrc + (size_t)(64 * p + r) * D_ + c * 4);
        }
        CPCOMMIT();
        CPWAIT_ALL();
        __syncthreads();
        #pragma unroll
        for (int it = 0; it < 8; it++) {
            int idx = tid + it * NT;
            int rl = idx >> 5, u = idx & 31;
            int r = 64 * p + rl;
            float4 f0 = *(const float4*)(smem + OFF_K + rl * 1024 + u * 32);
            float4 f1 = *(const float4*)(smem + OFF_K + rl * 1024 + u * 32 + 16);
            __half2 h01 = __floats2half2_rn(f0.x, f0.y);
            __half2 h23 = __floats2half2_rn(f0.z, f0.w);
            __half2 h45 = __floats2half2_rn(f1.x, f1.y);
            __half2 h67 = __floats2half2_rn(f1.z, f1.w);
            float2 g01 = __half22float2(h01), g23 = __half22float2(h23);
            float2 g45 = __half22float2(h45), g67 = __half22float2(h67);
            __half2 l01 = __floats2half2_rn(f0.x - g01.x, f0.y - g01.y);
            __half2 l23 = __floats2half2_rn(f0.z - g23.x, f0.w - g23.y);
            __half2 l45 = __floats2half2_rn(f1.x - g45.x, f1.y - g45.y);
            __half2 l67 = __floats2half2_rn(f1.z - g67.x, f1.w - g67.y);
            uint32_t off = r * 512 + ((u ^ (r & 7)) << 4);
            *(uint4*)(smem + off)       = make_uint4(*(uint32_t*)&h01, *(uint32_t*)&h23,
                                                     *(uint32_t*)&h45, *(uint32_t*)&h67);
            *(uint4*)(smem + off + QSP) = make_uint4(*(uint32_t*)&l01, *(uint32_t*)&l23,
                                                     *(uint32_t*)&l45, *(uint32_t*)&l67);
        }
        __syncthreads();
    }

    // ---- issue K(0): 256 d-rows x 8 units ----
    #pragma unroll
    for (int it = 0; it < 8; it++) {
        int idx = tid + it * NT;
        int r = idx >> 3, u = idx & 7;
        uint32_t dst = sb + OFF_K + r * 128 + ((u ^ (r & 7)) << 4);
        CPASYNC16(dst, khb + (size_t)r * S_ + u * 8);
    }
    CPCOMMIT();

    // ---- lane geometry ----
    const int mrow = lane & 7;
    const int rowA = warp * 16 + mrow + (((lane >> 3) & 1) << 3);
    const int hiA  = lane >> 4;
    const int krb  = ((lane >> 3) & 1) * 8 + (lane & 7);
    const int ul   = lane >> 4;

    uint32_t aQ[4];
    #pragma unroll
    for (int m = 0; m < 4; m++)
        aQ[m] = sb + rowA * 512 + ((((2 * m + hiA)) ^ mrow) << 4);

    uint32_t kbs[4], vrel[4];
    #pragma unroll
    for (int nn = 0; nn < 4; nn++)
        kbs[nn] = (uint32_t)(krb * 128 + (((2 * nn + ul) ^ (krb & 7)) << 4));
    #pragma unroll
    for (int i = 0; i < 4; i++)
        vrel[i] = (uint32_t)(krb * 512 + (((i * 2 + ul) ^ (krb & 7)) << 4));

    float O[32][4];
    #pragma unroll
    for (int i = 0; i < 32; i++) { O[i][0] = O[i][1] = O[i][2] = O[i][3] = 0.f; }
    float mr0 = -INFINITY, mr1 = -INFINITY, lr0 = 0.f, lr1 = 0.f;

    const int c2 = (lane & 3) * 2;
    const int g  = lane >> 2;

    for (int jt = 0; jt < ntiles; jt++) {
        const int kt = jt * 64;

        CPWAIT_ALL();          // K(jt) ready
        __syncthreads();       // all warps done GEMM2(jt-1) -> V buffer free

        // ---- issue V(jt): 64 j-rows x 32 units (overlaps GEMM1) ----
        #pragma unroll
        for (int it = 0; it < 8; it++) {
            int idx = tid + it * NT;
            int r = idx >> 5, u = idx & 31;
            uint32_t dst = sb + OFF_V + r * 512 + ((u >> 3) << 7)
                         + (((u & 7) ^ (r & 7)) << 4);
            CPASYNC16(dst, vhb + (size_t)(kt + r) * D_ + u * 8);
        }
        CPCOMMIT();

        // ---- GEMM1 (software-pipelined frags): S = Qhi*Khi + Qlo*Khi ----
        float s[8][4];
        #pragma unroll
        for (int i = 0; i < 8; i++) s[i][0] = s[i][1] = s[i][2] = s[i][3] = 0.f;

        {
            uint32_t A0[2][4], A1[2][4], BB[2][4];
            LDSM4(A0[0], aQ[0]);
            LDSM4(A1[0], aQ[0] + QSP);
            LDSM4T(BB[0], sb + OFF_K + kbs[0]);
            #pragma unroll
            for (int st = 0; st < 64; st++) {
                const int kk = st >> 2, nn = st & 3;
                const int cA = kk & 1, cB = st & 1;
                // prefetch next B frag into the other buffer (no WAR with current MMAs)
                {
                    const int stn = (st < 63) ? st + 1 : 63;
                    LDSM4T(BB[cB ^ 1],
                           sb + OFF_K + (stn >> 2) * 2048 + kbs[stn & 3]);
                }
                // prefetch next A frags one kk ahead
                if (nn == 2 && kk < 15) {
                    const uint32_t an = aQ[(kk + 1) & 3] + ((kk + 1) >> 2) * 128;
                    LDSM4(A0[cA ^ 1], an);
                    LDSM4(A1[cA ^ 1], an + QSP);
                }
                MMA(s[2*nn],   A0[cA], BB[cB][0], BB[cB][1]);
                MMA(s[2*nn],   A1[cA], BB[cB][0], BB[cB][1]);
                MMA(s[2*nn+1], A0[cA], BB[cB][2], BB[cB][3]);
                MMA(s[2*nn+1], A1[cA], BB[cB][2], BB[cB][3]);
            }
        }

        CPWAIT_ALL();          // V(jt) ready
        __syncthreads();       // all warps done GEMM1 -> K buffer free

        // ---- issue K(jt+1) NOW (overlaps softmax + GEMM2; clamped on last) ----
        {
            const int ktn = ((jt + 1 < ntiles) ? jt + 1 : jt) * 64;
            #pragma unroll
            for (int it = 0; it < 8; it++) {
                int idx = tid + it * NT;
                int r = idx >> 3, u = idx & 7;
                uint32_t dst = sb + OFF_K + r * 128 + ((u ^ (r & 7)) << 4);
                CPASYNC16(dst, khb + (size_t)r * S_ + ktn + u * 8);
            }
            CPCOMMIT();
        }

        // ---- tail guard + online softmax ----
        uint32_t Ph[8][2];
        {
            if (jt == ntiles - 1) {
                #pragma unroll
                for (int nf = 0; nf < 8; nf++) {
                    int col = kt + nf * 8 + c2;
                    if (col     >= nbv) { s[nf][0] = -1.0e9f; s[nf][2] = -1.0e9f; }
                    if (col + 1 >= nbv) { s[nf][1] = -1.0e9f; s[nf][3] = -1.0e9f; }
                }
            }
            float m0 = -INFINITY, m1 = -INFINITY;
            #pragma unroll
            for (int nf = 0; nf < 8; nf++) {
                m0 = fmaxf(m0, fmaxf(s[nf][0], s[nf][1]));
                m1 = fmaxf(m1, fmaxf(s[nf][2], s[nf][3]));
            }
            m0 = fmaxf(m0, __shfl_xor_sync(0xffffffffu, m0, 1));
            m0 = fmaxf(m0, __shfl_xor_sync(0xffffffffu, m0, 2));
            m1 = fmaxf(m1, __shfl_xor_sync(0xffffffffu, m1, 1));
            m1 = fmaxf(m1, __shfl_xor_sync(0xffffffffu, m1, 2));

            float mn0 = fmaxf(mr0, m0), mn1 = fmaxf(mr1, m1);
            float sc0 = exp2p((mr0 - mn0) * LOG2E);
            float sc1 = exp2p((mr1 - mn1) * LOG2E);
            mr0 = mn0; mr1 = mn1;
            float nb0 = -mn0 * LOG2E, nb1 = -mn1 * LOG2E;
            float rs0 = 0.f, rs1 = 0.f;

            #pragma unroll
            for (int nf = 0; nf < 8; nf++) {
                float p0 = exp2p(fmaf(s[nf][0], LOG2E, nb0));
                float p1 = exp2p(fmaf(s[nf][1], LOG2E, nb0));
                float p2 = exp2p(fmaf(s[nf][2], LOG2E, nb1));
                float p3 = exp2p(fmaf(s[nf][3], LOG2E, nb1));
                rs0 += p0 + p1;
                rs1 += p2 + p3;
                PACKH2(Ph[nf][0], p0, p1);
                PACKH2(Ph[nf][1], p2, p3);
            }
            lr0 = lr0 * sc0 + rs0;
            lr1 = lr1 * sc1 + rs1;

            if (__any_sync(0xffffffffu, (sc0 != 1.0f) || (sc1 != 1.0f))) {
                #pragma unroll
                for (int i = 0; i < 32; i++) {
                    O[i][0] *= sc0; O[i][1] *= sc0;
                    O[i][2] *= sc1; O[i][3] *= sc1;
                }
            }
        }

        // ---- GEMM2 (software-pipelined V frags): O += P * Vhi ----
        {
            uint32_t VB[2][4];
            LDSM4T(VB[0], sb + OFF_V + vrel[0]);
            #pragma unroll
            for (int st = 0; st < 64; st++) {
                const int kk = st >> 4, nn = st & 15;
                const int c = st & 1;
                {
                    const int stn = (st < 63) ? st + 1 : 63;
                    const int kk2 = stn >> 4, nn2 = stn & 15;
                    LDSM4T(VB[c ^ 1],
                           sb + OFF_V + kk2 * 8192 + vrel[nn2 & 3] + ((nn2 >> 2) << 7));
                }
                uint32_t ap[4] = { Ph[2*kk][0], Ph[2*kk][1],
                                   Ph[2*kk+1][0], Ph[2*kk+1][1] };
                MMA(O[2*nn],   ap, VB[c][0], VB[c][1]);
                MMA(O[2*nn+1], ap, VB[c][2], VB[c][3]);
            }
        }
    }
    CPWAIT_ALL();

    // ---- epilogue ----
    lr0 += __shfl_xor_sync(0xffffffffu, lr0, 1);
    lr0 += __shfl_xor_sync(0xffffffffu, lr0, 2);
    lr1 += __shfl_xor_sync(0xffffffffu, lr1, 1);
    lr1 += __shfl_xor_sync(0xffffffffu, lr1, 2);
    float inv0 = 1.f / (lr0 * 16.0f);
    float inv1 = 1.f / (lr1 * 16.0f);

    float* ob = out + (size_t)b * D_ * S_;
    const int qg = q0 + warp * 16 + g;
    #pragma unroll
    for (int nn = 0; nn < 32; nn++) {
        int dv = nn * 8 + c2;
        ob[(size_t)dv * S_ + qg]           = O[nn][0] * inv0;
        ob[(size_t)(dv + 1) * S_ + qg]     = O[nn][1] * inv0;
        ob[(size_t)dv * S_ + qg + 8]       = O[nn][2] * inv1;
        ob[(size_t)(dv + 1) * S_ + qg + 8] = O[nn][3] * inv1;
    }
}

// ================= launcher =================
extern "C" void kernel_launch(void* const* d_in, const int* in_sizes, int n_in,
                              void* d_out, int out_size)
{
    (void)in_sizes; (void)n_in; (void)out_size;
    const float* q    = (const float*)d_in[0];
    const float* k    = (const float*)d_in[1];
    const float* v    = (const float*)d_in[2];
    const int*   mask = (const int*)d_in[3];
    float* out = (float*)d_out;

    build_idx<<<B_, 256>>>(mask);
    {
        size_t total = (size_t)B_ * D_ * (S_ / 4);
        gather_k<<<(unsigned)((total + 255) / 256), 256>>>(k);
    }
    gather_v<<<dim3(S_ / 4, B_), 256>>>(v);

    cudaFuncSetAttribute(attn_hmma, cudaFuncAttributeMaxDynamicSharedMemorySize, SMEM_SZ);
    attn_hmma<<<dim3(S_ / 128, B_), NT, SMEM_SZ>>>(q, out);
}